// round 2
// baseline (speedup 1.0000x reference)
#include <cuda_runtime.h>
#include <math.h>

// ---------------- problem constants ----------------
#define BB   4
#define NN_  1024
#define DD   768
#define HH   12
#define DH   64
#define HID  2048
#define D3   2304          // 3*D
#define ROWS (BB*NN_)      // 4096
#define ZHN  (BB*HH)       // 48

// ---------------- scratch (static device memory; aliased regions) ----------------
// float offsets; lifetimes:
//   p   : steps 3-4
//   xm  : steps 7-10
//   ho  : h (steps 1-2) then o (steps 6-7)
//   qkv : steps 2-6, then h2 (steps 7-8) reuses its head
//   sc  : steps 4-6, then uv (8-9) and act (9-10) alias it
#define OFF_P    0L
#define OFF_XM   49152L
#define OFF_HO   3194880L
#define OFF_QKV  6340608L
#define OFF_SC   15777792L
#define SCRATCH_TOTAL 66109440L   // ~264 MB

__device__ float g_scratch[SCRATCH_TOTAL];

// ---------------- block reduce (256 threads = 8 warps) ----------------
__device__ __forceinline__ float blk_reduce(float v, float* sm, int op /*0=sum,1=max*/) {
    __syncthreads();
    #pragma unroll
    for (int o = 16; o > 0; o >>= 1) {
        float t = __shfl_xor_sync(0xffffffffu, v, o);
        v = op ? fmaxf(v, t) : (v + t);
    }
    int lane = threadIdx.x & 31, w = threadIdx.x >> 5;
    if (lane == 0) sm[w] = v;
    __syncthreads();
    float r = sm[0];
    #pragma unroll
    for (int i = 1; i < 8; i++) r = op ? fmaxf(r, sm[i]) : (r + sm[i]);
    return r;
}

// ---------------- LayerNorm (optionally fused residual-add, D=768) ----------------
__global__ __launch_bounds__(256) void ln_kernel(
    const float* __restrict__ x, const float* __restrict__ res,
    const float* __restrict__ g, const float* __restrict__ b,
    float* __restrict__ out, float* __restrict__ sum_out)
{
    __shared__ float sm[32];
    long row = blockIdx.x;
    int t = threadIdx.x;
    const float* xr = x + row * DD;
    float v[3];
    float s = 0.f;
    #pragma unroll
    for (int i = 0; i < 3; i++) {
        int idx = t + i * 256;
        float val = xr[idx];
        if (res) val += res[row * DD + idx];
        v[i] = val; s += val;
    }
    float mean = blk_reduce(s, sm, 0) * (1.f / 768.f);
    float vs = 0.f;
    #pragma unroll
    for (int i = 0; i < 3; i++) { float d = v[i] - mean; vs += d * d; }
    float var = blk_reduce(vs, sm, 0) * (1.f / 768.f);
    float rstd = rsqrtf(var + 1e-5f);
    #pragma unroll
    for (int i = 0; i < 3; i++) {
        int idx = t + i * 256;
        if (sum_out) sum_out[row * DD + idx] = v[i];
        out[row * DD + idx] = (v[i] - mean) * rstd * g[idx] + b[idx];
    }
}

// ---------------- p[b,h,n] = coords[b,n,:] . rel_w[h,:]  (C=3) ----------------
__global__ void p_kernel(const float* __restrict__ coords,
                         const float* __restrict__ rel_w,
                         float* __restrict__ p)
{
    int idx = blockIdx.x * 256 + threadIdx.x;
    if (idx >= ZHN * NN_) return;
    int n = idx & (NN_ - 1);
    int h = (idx >> 10) % HH;
    int b = idx / (HH * NN_);
    const float* c = coords + ((long)b * NN_ + n) * 3;
    const float* w = rel_w + h * 3;
    p[idx] = c[0] * w[0] + c[1] * w[1] + c[2] * w[2];
}

// ---------------- row softmax over 1024 (in place) ----------------
__global__ __launch_bounds__(256) void softmax_kernel(float* __restrict__ S)
{
    __shared__ float sm[32];
    long row = blockIdx.x;
    float* r = S + row * 1024;
    int t = threadIdx.x;
    float v[4];
    float m = -3.4e38f;
    #pragma unroll
    for (int i = 0; i < 4; i++) { v[i] = r[t + i * 256]; m = fmaxf(m, v[i]); }
    m = blk_reduce(m, sm, 1);
    float s = 0.f;
    #pragma unroll
    for (int i = 0; i < 4; i++) { v[i] = __expf(v[i] - m); s += v[i]; }
    s = blk_reduce(s, sm, 0);
    float inv = 1.f / s;
    #pragma unroll
    for (int i = 0; i < 4; i++) r[t + i * 256] = v[i] * inv;
}

// ---------------- SwiGLU: act = silu(u) * g ----------------
__global__ void swiglu_kernel(const float* __restrict__ uv, float* __restrict__ act)
{
    long idx = (long)blockIdx.x * 256 + threadIdx.x;
    long m = idx >> 11;          // / 2048
    int  j = (int)(idx & 2047);
    float u  = uv[m * 4096 + j];
    float gg = uv[m * 4096 + 2048 + j];
    float sig = 1.f / (1.f + __expf(-u));
    act[idx] = u * sig * gg;
}

// ---------------- generic tiled SGEMM ----------------
// C = alpha * A(MxK) * op(B) [+ biasSign*bias[col]] [+ residual], row-major, batched via grid.z
// BT=true : B is N x K row-major (C=A*B^T).  BT=false: B is K x N row-major.
template<int BM, int BN, int BK, int TM, int TN, bool BT>
__global__ __launch_bounds__(256) void gemm_kernel(
    const float* __restrict__ A, const float* __restrict__ B, float* __restrict__ C,
    int lda, int ldb, int ldc, int Hdim,
    long sAb, long sAh, long sBb, long sBh, long sCb, long sCh,
    int K, float alpha,
    const float* __restrict__ bias, float biasSign, long sBiasB, long sBiasH,
    const float* __restrict__ residual)
{
    int z = blockIdx.z;
    int zb = z / Hdim, zh = z % Hdim;
    A += zb * sAb + zh * sAh;
    B += zb * sBb + zh * sBh;
    C += zb * sCb + zh * sCh;
    const float* biasp = bias ? (bias + zb * sBiasB + zh * sBiasH) : nullptr;

    __shared__ float As[BK][BM];
    __shared__ float Bs[BK][BN];

    const int tid = threadIdx.x;
    constexpr int TCOLS = BN / TN;
    const int tcol = tid % TCOLS;
    const int trow = tid / TCOLS;

    const int row0 = blockIdx.y * BM;
    const int col0 = blockIdx.x * BN;

    float acc[TM][TN];
    #pragma unroll
    for (int i = 0; i < TM; i++)
        #pragma unroll
        for (int j = 0; j < TN; j++) acc[i][j] = 0.f;

    for (int k0 = 0; k0 < K; k0 += BK) {
        #pragma unroll
        for (int l = tid; l < BM * BK; l += 256) {
            int k = l % BK, m = l / BK;
            As[k][m] = A[(long)(row0 + m) * lda + k0 + k];
        }
        if (BT) {
            #pragma unroll
            for (int l = tid; l < BN * BK; l += 256) {
                int k = l % BK, n = l / BK;
                Bs[k][n] = B[(long)(col0 + n) * ldb + k0 + k];
            }
        } else {
            #pragma unroll
            for (int l = tid; l < BN * BK; l += 256) {
                int n = l % BN, k = l / BN;
                Bs[k][n] = B[(long)(k0 + k) * ldb + col0 + n];
            }
        }
        __syncthreads();
        #pragma unroll
        for (int kk = 0; kk < BK; kk++) {
            float a[TM], bf[TN];
            #pragma unroll
            for (int i = 0; i < TM; i += 4) {
                float4 t4 = *reinterpret_cast<const float4*>(&As[kk][trow * TM + i]);
                a[i] = t4.x; a[i + 1] = t4.y; a[i + 2] = t4.z; a[i + 3] = t4.w;
            }
            #pragma unroll
            for (int j = 0; j < TN; j += 4) {
                float4 t4 = *reinterpret_cast<const float4*>(&Bs[kk][tcol * TN + j]);
                bf[j] = t4.x; bf[j + 1] = t4.y; bf[j + 2] = t4.z; bf[j + 3] = t4.w;
            }
            #pragma unroll
            for (int i = 0; i < TM; i++)
                #pragma unroll
                for (int j = 0; j < TN; j++)
                    acc[i][j] = fmaf(a[i], bf[j], acc[i][j]);
        }
        __syncthreads();
    }

    // epilogue (float4 stores)
    #pragma unroll
    for (int i = 0; i < TM; i++) {
        long crow = row0 + (long)trow * TM + i;
        float* Crow = C + crow * ldc;
        const float* Rrow = residual ? (residual + crow * ldc) : nullptr;
        #pragma unroll
        for (int j0 = 0; j0 < TN; j0 += 4) {
            int ccol = col0 + tcol * TN + j0;
            float tmp[4];
            #pragma unroll
            for (int q = 0; q < 4; q++) {
                float val = alpha * acc[i][j0 + q];
                if (biasp) val += biasSign * biasp[ccol + q];
                if (Rrow)  val += Rrow[ccol + q];
                tmp[q] = val;
            }
            float4 vv; vv.x = tmp[0]; vv.y = tmp[1]; vv.z = tmp[2]; vv.w = tmp[3];
            *reinterpret_cast<float4*>(&Crow[ccol]) = vv;
        }
    }
}

// ---------------- launch ----------------
extern "C" void kernel_launch(void* const* d_in, const int* in_sizes, int n_in,
                              void* d_out, int out_size)
{
    const float* x      = (const float*)d_in[0];
    const float* coords = (const float*)d_in[1];
    const float* ln1_g  = (const float*)d_in[2];
    const float* ln1_b  = (const float*)d_in[3];
    const float* qkv_w  = (const float*)d_in[4];
    const float* qkv_b  = (const float*)d_in[5];
    const float* rel_w  = (const float*)d_in[6];
    const float* ln2_g  = (const float*)d_in[7];
    const float* ln2_b  = (const float*)d_in[8];
    const float* win_w  = (const float*)d_in[9];
    const float* win_b  = (const float*)d_in[10];
    const float* wout_w = (const float*)d_in[11];
    const float* wout_b = (const float*)d_in[12];
    float* out = (float*)d_out;

    float* S = nullptr;
    cudaGetSymbolAddress((void**)&S, g_scratch);
    float* p   = S + OFF_P;
    float* xm  = S + OFF_XM;
    float* ho  = S + OFF_HO;             // h, then o
    float* qkv = S + OFF_QKV;
    float* h2  = S + OFF_QKV;            // reuses qkv region after step 6
    float* sc  = S + OFF_SC;
    float* uv  = S + OFF_SC;             // reuses scores region after step 6
    float* act = S + OFF_SC + 16777216L; // after uv within scores region

    // 1) h = LN1(x)
    ln_kernel<<<ROWS, 256>>>(x, nullptr, ln1_g, ln1_b, ho, nullptr);

    // 2) qkv = h @ qkv_w^T + qkv_b    (4096 x 2304, K=768)
    gemm_kernel<128,128,16,8,8,true><<<dim3(D3/128, ROWS/128, 1), 256>>>(
        ho, qkv_w, qkv, DD, DD, D3, 1,
        0,0, 0,0, 0,0,
        DD, 1.f, qkv_b, 1.f, 0, 0, nullptr);

    // 3) p[b,h,n]
    p_kernel<<<(ZHN*NN_)/256, 256>>>(coords, rel_w, p);

    // 4) scores[z] = 0.125 * Q_z @ K_z^T - p_z[col]    (48 x 1024 x 1024, K=64)
    //    (+p_i term is constant along softmax axis and cancels)
    gemm_kernel<128,128,16,8,8,true><<<dim3(NN_/128, NN_/128, ZHN), 256>>>(
        qkv, qkv + DD, sc, D3, D3, NN_, HH,
        (long)NN_*D3, 64,  (long)NN_*D3, 64,  (long)HH*NN_*NN_, (long)NN_*NN_,
        DH, 0.125f, p, -1.f, (long)HH*NN_, (long)NN_, nullptr);

    // 5) softmax rows (in place)
    softmax_kernel<<<ZHN*NN_, 256>>>(sc);

    // 6) o[b,i,h*64+d] = P_z @ V_z   (M=1024, N=64, K=1024; B non-transposed)
    gemm_kernel<128,64,16,8,4,false><<<dim3(1, NN_/128, ZHN), 256>>>(
        sc, qkv + 2*DD, ho, NN_, D3, DD, HH,
        (long)HH*NN_*NN_, (long)NN_*NN_,  (long)NN_*D3, 64,  (long)NN_*DD, 64,
        NN_, 1.f, nullptr, 0.f, 0, 0, nullptr);

    // 7) xm = x + o ; h2 = LN2(xm)   (h2 overwrites dead qkv region)
    ln_kernel<<<ROWS, 256>>>(x, ho, ln2_g, ln2_b, h2, xm);

    // 8) uv = h2 @ win_w^T + win_b   (4096 x 4096, K=768)  (uv overwrites dead scores)
    gemm_kernel<128,128,16,8,8,true><<<dim3((2*HID)/128, ROWS/128, 1), 256>>>(
        h2, win_w, uv, DD, DD, 2*HID, 1,
        0,0, 0,0, 0,0,
        DD, 1.f, win_b, 1.f, 0, 0, nullptr);

    // 9) act = silu(u) * g
    swiglu_kernel<<<(ROWS*HID)/256, 256>>>(uv, act);

    // 10) out = act @ wout_w^T + wout_b + xm   (4096 x 768, K=2048)
    gemm_kernel<128,128,16,8,8,true><<<dim3(DD/128, ROWS/128, 1), 256>>>(
        act, wout_w, out, HID, HID, DD, 1,
        0,0, 0,0, 0,0,
        HID, 1.f, wout_b, 1.f, 0, 0, xm);
}

// round 3
// speedup vs baseline: 4.1735x; 4.1735x over previous
#include <cuda_runtime.h>
#include <math.h>
#include <stdint.h>

// ---------------- problem constants ----------------
#define BB   4
#define NN_  1024
#define DD   768
#define HH   12
#define DH   64
#define HID  2048
#define D3   2304          // 3*D
#define ROWS (BB*NN_)      // 4096
#define ZHN  (BB*HH)       // 48

// ---------------- scratch (static device memory; aliased regions) ----------------
#define OFF_P    0L
#define OFF_XM   49152L
#define OFF_HO   3194880L
#define OFF_QKV  6340608L
#define OFF_SC   15777792L
#define SCRATCH_TOTAL 66109440L   // ~264 MB

__device__ float g_scratch[SCRATCH_TOTAL];

// ---------------- PTX helpers ----------------
#define CP_ASYNC16(dst, src) asm volatile("cp.async.cg.shared.global [%0], [%1], 16;\n" :: "r"(dst), "l"(src))
#define CP_COMMIT()  asm volatile("cp.async.commit_group;\n")
#define CP_WAIT1()   asm volatile("cp.async.wait_group 1;\n" ::: "memory")
#define CP_WAIT0()   asm volatile("cp.async.wait_group 0;\n" ::: "memory")
#define F2TF32(x)    asm volatile("cvt.rna.tf32.f32 %0, %0;\n" : "+r"(x))

__device__ __forceinline__ void ldsm4(uint32_t& r0, uint32_t& r1, uint32_t& r2, uint32_t& r3, uint32_t addr) {
    asm volatile("ldmatrix.sync.aligned.m8n8.x4.shared.b16 {%0,%1,%2,%3}, [%4];\n"
                 : "=r"(r0), "=r"(r1), "=r"(r2), "=r"(r3) : "r"(addr));
}
__device__ __forceinline__ void mma_tf32(float* c, const uint32_t* a, const uint32_t* b) {
    asm volatile(
        "mma.sync.aligned.m16n8k8.row.col.f32.tf32.tf32.f32 "
        "{%0,%1,%2,%3},{%4,%5,%6,%7},{%8,%9},{%0,%1,%2,%3};\n"
        : "+f"(c[0]), "+f"(c[1]), "+f"(c[2]), "+f"(c[3])
        : "r"(a[0]), "r"(a[1]), "r"(a[2]), "r"(a[3]), "r"(b[0]), "r"(b[1]));
}

// ---------------- block reduce ----------------
__device__ __forceinline__ float blk_reduce(float v, float* sm, int op) {
    __syncthreads();
    #pragma unroll
    for (int o = 16; o > 0; o >>= 1) {
        float t = __shfl_xor_sync(0xffffffffu, v, o);
        v = op ? fmaxf(v, t) : (v + t);
    }
    int lane = threadIdx.x & 31, w = threadIdx.x >> 5;
    if (lane == 0) sm[w] = v;
    __syncthreads();
    float r = sm[0];
    #pragma unroll
    for (int i = 1; i < 8; i++) r = op ? fmaxf(r, sm[i]) : (r + sm[i]);
    return r;
}

// ---------------- LayerNorm ----------------
__global__ __launch_bounds__(256) void ln_kernel(
    const float* __restrict__ x, const float* __restrict__ res,
    const float* __restrict__ g, const float* __restrict__ b,
    float* __restrict__ out, float* __restrict__ sum_out)
{
    __shared__ float sm[32];
    long row = blockIdx.x;
    int t = threadIdx.x;
    const float* xr = x + row * DD;
    float v[3];
    float s = 0.f;
    #pragma unroll
    for (int i = 0; i < 3; i++) {
        int idx = t + i * 256;
        float val = xr[idx];
        if (res) val += res[row * DD + idx];
        v[i] = val; s += val;
    }
    float mean = blk_reduce(s, sm, 0) * (1.f / 768.f);
    float vs = 0.f;
    #pragma unroll
    for (int i = 0; i < 3; i++) { float d = v[i] - mean; vs += d * d; }
    float var = blk_reduce(vs, sm, 0) * (1.f / 768.f);
    float rstd = rsqrtf(var + 1e-5f);
    #pragma unroll
    for (int i = 0; i < 3; i++) {
        int idx = t + i * 256;
        if (sum_out) sum_out[row * DD + idx] = v[i];
        out[row * DD + idx] = (v[i] - mean) * rstd * g[idx] + b[idx];
    }
}

// ---------------- p[b,h,n] ----------------
__global__ void p_kernel(const float* __restrict__ coords,
                         const float* __restrict__ rel_w,
                         float* __restrict__ p)
{
    int idx = blockIdx.x * 256 + threadIdx.x;
    if (idx >= ZHN * NN_) return;
    int n = idx & (NN_ - 1);
    int h = (idx >> 10) % HH;
    int b = idx / (HH * NN_);
    const float* c = coords + ((long)b * NN_ + n) * 3;
    const float* w = rel_w + h * 3;
    p[idx] = c[0] * w[0] + c[1] * w[1] + c[2] * w[2];
}

// ---------------- row softmax over 1024 (in place) ----------------
__global__ __launch_bounds__(256) void softmax_kernel(float* __restrict__ S)
{
    __shared__ float sm[32];
    long row = blockIdx.x;
    float* r = S + row * 1024;
    int t = threadIdx.x;
    float v[4];
    float m = -3.4e38f;
    #pragma unroll
    for (int i = 0; i < 4; i++) { v[i] = r[t + i * 256]; m = fmaxf(m, v[i]); }
    m = blk_reduce(m, sm, 1);
    float s = 0.f;
    #pragma unroll
    for (int i = 0; i < 4; i++) { v[i] = __expf(v[i] - m); s += v[i]; }
    s = blk_reduce(s, sm, 0);
    float inv = 1.f / s;
    #pragma unroll
    for (int i = 0; i < 4; i++) r[t + i * 256] = v[i] * inv;
}

// ---------------- SwiGLU ----------------
__global__ void swiglu_kernel(const float* __restrict__ uv, float* __restrict__ act)
{
    long idx = (long)blockIdx.x * 256 + threadIdx.x;
    long m = idx >> 11;
    int  j = (int)(idx & 2047);
    float u  = uv[m * 4096 + j];
    float gg = uv[m * 4096 + 2048 + j];
    float sig = 1.f / (1.f + __expf(-u));
    act[idx] = u * sig * gg;
}

// =====================================================================
// tf32 tensor-core GEMM.
// C = alpha * A(MxK) * op(B) [+ biasSign*bias[col]] [+ residual]
// BT=true : B is NxK row-major (C = A*B^T), both A,B loaded via cp.async.
// BT=false: B is KxN row-major; B transposed into smem synchronously
//           (requires BN=64, BK=16, 256 threads).
// Smem layout (both operands): [row][k] with row stride LDS_=20 floats —
// conflict-free for ldmatrix (offsets 0,80,160.. mod 128 hit disjoint
// 16B windows).
// =====================================================================
template<int BM, int BN, int WM, int WN, bool BT>
__global__ __launch_bounds__(256) void tgemm(
    const float* __restrict__ A, const float* __restrict__ B, float* __restrict__ C,
    int lda, int ldb, int ldc, int Hdim,
    long sAb, long sAh, long sBb, long sBh, long sCb, long sCh,
    int K, float alpha,
    const float* __restrict__ bias, float biasSign, long sBiasB, long sBiasH,
    const float* __restrict__ residual)
{
    constexpr int BK = 16;
    constexpr int LDS_ = 20;                 // padded row stride (floats)
    constexpr int WARPS_N = BN / WN;
    constexpr int MF = WM / 16;              // A fragment groups per warp
    constexpr int NG = WN / 16;              // B fragment groups per warp (each -> 2 n8 frags)
    constexpr int AF4 = BM * BK / 1024;      // float4 loads per thread for A
    constexpr int BF4 = BN * BK / 1024;      // for B (BT=true)
    constexpr uint32_t ASZ = BM * LDS_ * 4;  // stage size bytes
    constexpr uint32_t BSZ = BN * LDS_ * 4;

    __shared__ float As[2][BM * LDS_];
    __shared__ float Bs[2][BN * LDS_];

    const int tid  = threadIdx.x;
    const int lane = tid & 31;
    const int warp = tid >> 5;
    const int wm = warp / WARPS_N;
    const int wn = warp % WARPS_N;

    const int z  = blockIdx.z;
    const int zb = z / Hdim, zh = z % Hdim;
    A += zb * sAb + zh * sAh;
    B += zb * sBb + zh * sBh;
    C += zb * sCb + zh * sCh;
    const float* biasp = bias ? (bias + zb * sBiasB + zh * sBiasH) : nullptr;

    const int row0 = blockIdx.y * BM;
    const int col0 = blockIdx.x * BN;

    const uint32_t asu = (uint32_t)__cvta_generic_to_shared(&As[0][0]);
    const uint32_t bsu = (uint32_t)__cvta_generic_to_shared(&Bs[0][0]);

    float acc[MF][NG * 2][4];
    #pragma unroll
    for (int i = 0; i < MF; i++)
        #pragma unroll
        for (int j = 0; j < NG * 2; j++)
            #pragma unroll
            for (int q = 0; q < 4; q++) acc[i][j][q] = 0.f;

    const int KT = K / BK;

    // ---- prefetch helper (stage s, k-tile kt) ----
    auto prefetch = [&](int s, int kt) {
        const float* Ag = A + (long)row0 * lda + kt * BK;
        #pragma unroll
        for (int i = 0; i < AF4; i++) {
            int l = tid + 256 * i;
            int r = l >> 2, c = (l & 3) << 2;
            CP_ASYNC16(asu + (uint32_t)s * ASZ + (uint32_t)(r * LDS_ + c) * 4,
                       Ag + (long)r * lda + c);
        }
        if (BT) {
            const float* Bg = B + (long)col0 * ldb + kt * BK;
            #pragma unroll
            for (int i = 0; i < BF4; i++) {
                int l = tid + 256 * i;
                int r = l >> 2, c = (l & 3) << 2;
                CP_ASYNC16(bsu + (uint32_t)s * BSZ + (uint32_t)(r * LDS_ + c) * 4,
                           Bg + (long)r * ldb + c);
            }
        } else {
            // B is KxN; transpose into Bs[n][k]. BN=64, BK=16 -> 256 float4's.
            const float* Bg = B + (long)(kt * BK) * ldb + col0;
            int k  = tid >> 4;
            int n4 = (tid & 15) << 2;
            float4 v = *reinterpret_cast<const float4*>(Bg + (long)k * ldb + n4);
            float* bp = &Bs[s][0];
            bp[(n4 + 0) * LDS_ + k] = v.x;
            bp[(n4 + 1) * LDS_ + k] = v.y;
            bp[(n4 + 2) * LDS_ + k] = v.z;
            bp[(n4 + 3) * LDS_ + k] = v.w;
        }
        CP_COMMIT();
    };

    prefetch(0, 0);

    for (int kt = 0; kt < KT; kt++) {
        if (kt + 1 < KT) { prefetch((kt + 1) & 1, kt + 1); CP_WAIT1(); }
        else             { CP_WAIT0(); }
        __syncthreads();

        const uint32_t ab = asu + (uint32_t)(kt & 1) * ASZ;
        const uint32_t bb = bsu + (uint32_t)(kt & 1) * BSZ;

        #pragma unroll
        for (int k8 = 0; k8 < 2; k8++) {
            uint32_t af[MF][4];
            #pragma unroll
            for (int im = 0; im < MF; im++) {
                int m = wm * WM + im * 16 + (lane & 7) + ((lane >> 3) & 1) * 8;
                uint32_t addr = ab + (uint32_t)(m * LDS_) * 4 + k8 * 32 + ((lane >> 4) & 1) * 16;
                ldsm4(af[im][0], af[im][1], af[im][2], af[im][3], addr);
                F2TF32(af[im][0]); F2TF32(af[im][1]); F2TF32(af[im][2]); F2TF32(af[im][3]);
            }
            #pragma unroll
            for (int ig = 0; ig < NG; ig++) {
                uint32_t bf[4];
                int n = wn * WN + ig * 16 + (lane & 7) + ((lane >> 4) & 1) * 8;
                uint32_t addr = bb + (uint32_t)(n * LDS_) * 4 + k8 * 32 + ((lane >> 3) & 1) * 16;
                ldsm4(bf[0], bf[1], bf[2], bf[3], addr);
                F2TF32(bf[0]); F2TF32(bf[1]); F2TF32(bf[2]); F2TF32(bf[3]);
                #pragma unroll
                for (int im = 0; im < MF; im++) {
                    mma_tf32(acc[im][ig * 2 + 0], af[im], bf + 0);
                    mma_tf32(acc[im][ig * 2 + 1], af[im], bf + 2);
                }
            }
        }
        __syncthreads();
    }

    // ---- epilogue ----
    #pragma unroll
    for (int im = 0; im < MF; im++) {
        int mrow = row0 + wm * WM + im * 16 + (lane >> 2);
        #pragma unroll
        for (int jg = 0; jg < NG * 2; jg++) {
            int ncol = col0 + wn * WN + (jg >> 1) * 16 + (jg & 1) * 8 + 2 * (lane & 3);
            float b0 = 0.f, b1 = 0.f;
            if (biasp) { b0 = biasSign * biasp[ncol]; b1 = biasSign * biasp[ncol + 1]; }
            #pragma unroll
            for (int half = 0; half < 2; half++) {
                long r = mrow + half * 8;
                float v0 = alpha * acc[im][jg][half * 2 + 0] + b0;
                float v1 = alpha * acc[im][jg][half * 2 + 1] + b1;
                if (residual) {
                    v0 += residual[r * ldc + ncol];
                    v1 += residual[r * ldc + ncol + 1];
                }
                float2 vv; vv.x = v0; vv.y = v1;
                *reinterpret_cast<float2*>(&C[r * ldc + ncol]) = vv;
            }
        }
    }
}

// ---------------- launch ----------------
extern "C" void kernel_launch(void* const* d_in, const int* in_sizes, int n_in,
                              void* d_out, int out_size)
{
    const float* x      = (const float*)d_in[0];
    const float* coords = (const float*)d_in[1];
    const float* ln1_g  = (const float*)d_in[2];
    const float* ln1_b  = (const float*)d_in[3];
    const float* qkv_w  = (const float*)d_in[4];
    const float* qkv_b  = (const float*)d_in[5];
    const float* rel_w  = (const float*)d_in[6];
    const float* ln2_g  = (const float*)d_in[7];
    const float* ln2_b  = (const float*)d_in[8];
    const float* win_w  = (const float*)d_in[9];
    const float* win_b  = (const float*)d_in[10];
    const float* wout_w = (const float*)d_in[11];
    const float* wout_b = (const float*)d_in[12];
    float* out = (float*)d_out;

    float* S = nullptr;
    cudaGetSymbolAddress((void**)&S, g_scratch);
    float* p   = S + OFF_P;
    float* xm  = S + OFF_XM;
    float* ho  = S + OFF_HO;             // h, then o
    float* qkv = S + OFF_QKV;
    float* h2  = S + OFF_QKV;            // reuses qkv region after step 6
    float* sc  = S + OFF_SC;
    float* uv  = S + OFF_SC;             // reuses scores region
    float* act = S + OFF_SC + 16777216L;

    // 1) h = LN1(x)
    ln_kernel<<<ROWS, 256>>>(x, nullptr, ln1_g, ln1_b, ho, nullptr);

    // 2) qkv = h @ qkv_w^T + qkv_b    (4096 x 2304, K=768)
    tgemm<128,128,64,32,true><<<dim3(D3/128, ROWS/128, 1), 256>>>(
        ho, qkv_w, qkv, DD, DD, D3, 1,
        0,0, 0,0, 0,0,
        DD, 1.f, qkv_b, 1.f, 0, 0, nullptr);

    // 3) p[b,h,n]
    p_kernel<<<(ZHN*NN_)/256, 256>>>(coords, rel_w, p);

    // 4) scores[z] = 0.125 * Q_z @ K_z^T - p_z[col]   (+p_i cancels in softmax)
    tgemm<128,128,64,32,true><<<dim3(NN_/128, NN_/128, ZHN), 256>>>(
        qkv, qkv + DD, sc, D3, D3, NN_, HH,
        (long)NN_*D3, 64,  (long)NN_*D3, 64,  (long)HH*NN_*NN_, (long)NN_*NN_,
        DH, 0.125f, p, -1.f, (long)HH*NN_, (long)NN_, nullptr);

    // 5) softmax rows
    softmax_kernel<<<ZHN*NN_, 256>>>(sc);

    // 6) o = P_z @ V_z   (M=1024, N=64, K=1024; B is KxN)
    tgemm<128,64,32,32,false><<<dim3(1, NN_/128, ZHN), 256>>>(
        sc, qkv + 2*DD, ho, NN_, D3, DD, HH,
        (long)HH*NN_*NN_, (long)NN_*NN_,  (long)NN_*D3, 64,  (long)NN_*DD, 64,
        NN_, 1.f, nullptr, 0.f, 0, 0, nullptr);

    // 7) xm = x + o ; h2 = LN2(xm)
    ln_kernel<<<ROWS, 256>>>(x, ho, ln2_g, ln2_b, h2, xm);

    // 8) uv = h2 @ win_w^T + win_b   (4096 x 4096, K=768)
    tgemm<128,128,64,32,true><<<dim3((2*HID)/128, ROWS/128, 1), 256>>>(
        h2, win_w, uv, DD, DD, 2*HID, 1,
        0,0, 0,0, 0,0,
        DD, 1.f, win_b, 1.f, 0, 0, nullptr);

    // 9) act = silu(u) * g
    swiglu_kernel<<<(ROWS*HID)/256, 256>>>(uv, act);

    // 10) out = act @ wout_w^T + wout_b + xm   (4096 x 768, K=2048)
    tgemm<128,128,64,32,true><<<dim3(DD/128, ROWS/128, 1), 256>>>(
        act, wout_w, out, HID, HID, DD, 1,
        0,0, 0,0, 0,0,
        HID, 1.f, wout_b, 1.f, 0, 0, xm);
}

// round 5
// speedup vs baseline: 4.8078x; 1.1520x over previous
#include <cuda_runtime.h>
#include <math.h>
#include <stdint.h>

// ---------------- problem constants ----------------
#define BB   4
#define NN_  1024
#define DD   768
#define HH   12
#define DH   64
#define HID  2048
#define D3   2304          // 3*D
#define ROWS (BB*NN_)      // 4096
#define ZHN  (BB*HH)       // 48

// ---------------- scratch (static device memory; aliased regions) ----------------
#define OFF_P    0L
#define OFF_XM   49152L
#define OFF_HO   3194880L
#define OFF_QKV  6340608L
#define OFF_SC   15777792L            // uv (16.7M) then act (8.4M)
#define SCRATCH_TOTAL 40943616L       // ~164 MB

__device__ float g_scratch[SCRATCH_TOTAL];

// ---------------- PTX helpers ----------------
#define CP_ASYNC16(dst, src) asm volatile("cp.async.cg.shared.global [%0], [%1], 16;\n" :: "r"(dst), "l"(src))
#define CP_COMMIT()  asm volatile("cp.async.commit_group;\n")
#define CP_WAIT1()   asm volatile("cp.async.wait_group 1;\n" ::: "memory")
#define CP_WAIT0()   asm volatile("cp.async.wait_group 0;\n" ::: "memory")
#define F2TF32(x)    asm volatile("cvt.rna.tf32.f32 %0, %0;\n" : "+r"(x))

__device__ __forceinline__ void ldsm4(uint32_t& r0, uint32_t& r1, uint32_t& r2, uint32_t& r3, uint32_t addr) {
    asm volatile("ldmatrix.sync.aligned.m8n8.x4.shared.b16 {%0,%1,%2,%3}, [%4];\n"
                 : "=r"(r0), "=r"(r1), "=r"(r2), "=r"(r3) : "r"(addr));
}
__device__ __forceinline__ void mma_tf32(float* c, const uint32_t* a, const uint32_t* b) {
    asm volatile(
        "mma.sync.aligned.m16n8k8.row.col.f32.tf32.tf32.f32 "
        "{%0,%1,%2,%3},{%4,%5,%6,%7},{%8,%9},{%0,%1,%2,%3};\n"
        : "+f"(c[0]), "+f"(c[1]), "+f"(c[2]), "+f"(c[3])
        : "r"(a[0]), "r"(a[1]), "r"(a[2]), "r"(a[3]), "r"(b[0]), "r"(b[1]));
}

// ---------------- block reduce ----------------
__device__ __forceinline__ float blk_reduce(float v, float* sm, int op) {
    __syncthreads();
    #pragma unroll
    for (int o = 16; o > 0; o >>= 1) {
        float t = __shfl_xor_sync(0xffffffffu, v, o);
        v = op ? fmaxf(v, t) : (v + t);
    }
    int lane = threadIdx.x & 31, w = threadIdx.x >> 5;
    if (lane == 0) sm[w] = v;
    __syncthreads();
    float r = sm[0];
    #pragma unroll
    for (int i = 1; i < 8; i++) r = op ? fmaxf(r, sm[i]) : (r + sm[i]);
    return r;
}

// ---------------- LayerNorm ----------------
__global__ __launch_bounds__(256) void ln_kernel(
    const float* __restrict__ x, const float* __restrict__ res,
    const float* __restrict__ g, const float* __restrict__ b,
    float* __restrict__ out, float* __restrict__ sum_out)
{
    __shared__ float sm[32];
    long row = blockIdx.x;
    int t = threadIdx.x;
    const float* xr = x + row * DD;
    float v[3];
    float s = 0.f;
    #pragma unroll
    for (int i = 0; i < 3; i++) {
        int idx = t + i * 256;
        float val = xr[idx];
        if (res) val += res[row * DD + idx];
        v[i] = val; s += val;
    }
    float mean = blk_reduce(s, sm, 0) * (1.f / 768.f);
    float vs = 0.f;
    #pragma unroll
    for (int i = 0; i < 3; i++) { float d = v[i] - mean; vs += d * d; }
    float var = blk_reduce(vs, sm, 0) * (1.f / 768.f);
    float rstd = rsqrtf(var + 1e-5f);
    #pragma unroll
    for (int i = 0; i < 3; i++) {
        int idx = t + i * 256;
        if (sum_out) sum_out[row * DD + idx] = v[i];
        out[row * DD + idx] = (v[i] - mean) * rstd * g[idx] + b[idx];
    }
}

// ---------------- p[b,h,n] ----------------
__global__ void p_kernel(const float* __restrict__ coords,
                         const float* __restrict__ rel_w,
                         float* __restrict__ p)
{
    int idx = blockIdx.x * 256 + threadIdx.x;
    if (idx >= ZHN * NN_) return;
    int n = idx & (NN_ - 1);
    int h = (idx >> 10) % HH;
    int b = idx / (HH * NN_);
    const float* c = coords + ((long)b * NN_ + n) * 3;
    const float* w = rel_w + h * 3;
    p[idx] = c[0] * w[0] + c[1] * w[1] + c[2] * w[2];
}

// ---------------- SwiGLU ----------------
__global__ void swiglu_kernel(const float* __restrict__ uv, float* __restrict__ act)
{
    long idx = (long)blockIdx.x * 256 + threadIdx.x;
    long m = idx >> 11;
    int  j = (int)(idx & 2047);
    float u  = uv[m * 4096 + j];
    float gg = uv[m * 4096 + 2048 + j];
    float sig = 1.f / (1.f + __expf(-u));
    act[idx] = u * sig * gg;
}

// =====================================================================
// Fused flash attention (tf32 MMA).
// One block = (z = b*H + h, m-tile of 128 query rows). 256 threads = 8 warps,
// each warp owns 16 query rows. Loops over 16 KV tiles of 64 keys.
// S = 0.125 * Q K^T - p[key]  (row-constant +p_i cancels in softmax)
// Online softmax; O = P V accumulated in registers; write O/l at the end.
// =====================================================================
struct FaSmem {
    float Qs[128 * 68];        // [qrow][d]
    float Ks[2][64 * 68];      // [key][d]
    float Vst[2][64 * 68];     // [key][d]  (staging)
    float Vt[64 * 68];         // [d][key]  (transposed for B operand)
    float Ps[8][16 * 68];      // per-warp P tile [qrow][key]
    float psc[2][64];          // p bias per key
};
#define FA_SMEM_BYTES (sizeof(FaSmem))

__global__ __launch_bounds__(256) void fa_kernel(
    const float* __restrict__ qkv, const float* __restrict__ p,
    float* __restrict__ o)
{
    extern __shared__ float smf[];
    FaSmem* sm = reinterpret_cast<FaSmem*>(smf);
    const int tid = threadIdx.x, lane = tid & 31, warp = tid >> 5;
    const int mt = blockIdx.x;       // 0..7
    const int z  = blockIdx.y;       // 0..47
    const int zb = z / HH, zh = z % HH;

    const float* Qg = qkv + ((long)zb * NN_ + mt * 128) * D3 + zh * 64;
    const float* Kg = qkv + (long)zb * NN_ * D3 + DD + zh * 64;
    const float* Vg = qkv + (long)zb * NN_ * D3 + 2 * DD + zh * 64;
    const float* pg = p + (long)z * NN_;

    const uint32_t qsu  = (uint32_t)__cvta_generic_to_shared(sm->Qs);
    const uint32_t ksu  = (uint32_t)__cvta_generic_to_shared(sm->Ks[0]);
    const uint32_t vsu  = (uint32_t)__cvta_generic_to_shared(sm->Vst[0]);
    const uint32_t vtu  = (uint32_t)__cvta_generic_to_shared(sm->Vt);
    const uint32_t psu  = (uint32_t)__cvta_generic_to_shared(sm->Ps[warp]);
    const uint32_t pscu = (uint32_t)__cvta_generic_to_shared(sm->psc[0]);
    constexpr uint32_t KVB = 64 * 68 * 4;   // one KV stage in bytes

    auto prep = [&](int s, int j) {
        #pragma unroll
        for (int i = 0; i < 4; i++) {
            int l = tid + 256 * i;
            int r = l >> 4, c4 = (l & 15) << 2;
            CP_ASYNC16(ksu + (uint32_t)s * KVB + (uint32_t)(r * 68 + c4) * 4,
                       Kg + (long)(j * 64 + r) * D3 + c4);
            CP_ASYNC16(vsu + (uint32_t)s * KVB + (uint32_t)(r * 68 + c4) * 4,
                       Vg + (long)(j * 64 + r) * D3 + c4);
        }
        if (tid < 16)
            CP_ASYNC16(pscu + (uint32_t)s * 256 + tid * 16, pg + j * 64 + tid * 4);
        CP_COMMIT();
    };

    // Q load (joins group 0 with prep(0,0))
    #pragma unroll
    for (int i = 0; i < 8; i++) {
        int l = tid + 256 * i;
        int r = l >> 4, c4 = (l & 15) << 2;
        CP_ASYNC16(qsu + (uint32_t)(r * 68 + c4) * 4, Qg + (long)r * D3 + c4);
    }
    prep(0, 0);

    float m0 = -1e30f, m1 = -1e30f, l0 = 0.f, l1 = 0.f;
    float oacc[4][2][4];
    #pragma unroll
    for (int a = 0; a < 4; a++)
        #pragma unroll
        for (int b = 0; b < 2; b++)
            #pragma unroll
            for (int q = 0; q < 4; q++) oacc[a][b][q] = 0.f;

    for (int j = 0; j < 16; j++) {
        const int s = j & 1;
        __syncthreads();                       // prev compute done: stage s^1 free
        if (j < 15) { prep(s ^ 1, j + 1); CP_WAIT1(); }
        else        { CP_WAIT0(); }
        __syncthreads();                       // stage s data visible block-wide

        // transpose Vst[s] -> Vt[d][key]
        {
            int key = tid & 63, cg = tid >> 6;
            #pragma unroll
            for (int i = 0; i < 4; i++) {
                int c4 = cg * 4 + 16 * i;
                float4 v = *reinterpret_cast<const float4*>(&sm->Vst[s][key * 68 + c4]);
                sm->Vt[(c4 + 0) * 68 + key] = v.x;
                sm->Vt[(c4 + 1) * 68 + key] = v.y;
                sm->Vt[(c4 + 2) * 68 + key] = v.z;
                sm->Vt[(c4 + 3) * 68 + key] = v.w;
            }
        }
        __syncthreads();

        // ---- S = Q K^T (warp: 16 rows x 64 keys) ----
        float sacc[4][2][4];
        #pragma unroll
        for (int a = 0; a < 4; a++)
            #pragma unroll
            for (int b = 0; b < 2; b++)
                #pragma unroll
                for (int q = 0; q < 4; q++) sacc[a][b][q] = 0.f;

        const uint32_t ksb = ksu + (uint32_t)s * KVB;
        #pragma unroll
        for (int k8 = 0; k8 < 8; k8++) {
            uint32_t af[4];
            {
                int m = warp * 16 + (lane & 7) + ((lane >> 3) & 1) * 8;
                uint32_t addr = qsu + (uint32_t)(m * 68) * 4 + k8 * 32 + ((lane >> 4) & 1) * 16;
                ldsm4(af[0], af[1], af[2], af[3], addr);
                F2TF32(af[0]); F2TF32(af[1]); F2TF32(af[2]); F2TF32(af[3]);
            }
            #pragma unroll
            for (int ig = 0; ig < 4; ig++) {
                uint32_t bf[4];
                int n = ig * 16 + (lane & 7) + ((lane >> 4) & 1) * 8;
                uint32_t addr = ksb + (uint32_t)(n * 68) * 4 + k8 * 32 + ((lane >> 3) & 1) * 16;
                ldsm4(bf[0], bf[1], bf[2], bf[3], addr);
                F2TF32(bf[0]); F2TF32(bf[1]); F2TF32(bf[2]); F2TF32(bf[3]);
                mma_tf32(sacc[ig][0], af, bf + 0);
                mma_tf32(sacc[ig][1], af, bf + 2);
            }
        }

        // ---- scale + key bias ----
        #pragma unroll
        for (int ig = 0; ig < 4; ig++)
            #pragma unroll
            for (int hf = 0; hf < 2; hf++) {
                int cb = ig * 16 + hf * 8 + 2 * (lane & 3);
                float p0 = sm->psc[s][cb], p1 = sm->psc[s][cb + 1];
                sacc[ig][hf][0] = sacc[ig][hf][0] * 0.125f - p0;
                sacc[ig][hf][1] = sacc[ig][hf][1] * 0.125f - p1;
                sacc[ig][hf][2] = sacc[ig][hf][2] * 0.125f - p0;
                sacc[ig][hf][3] = sacc[ig][hf][3] * 0.125f - p1;
            }

        // ---- online softmax ----
        float mx0 = -1e30f, mx1 = -1e30f;
        #pragma unroll
        for (int ig = 0; ig < 4; ig++)
            #pragma unroll
            for (int hf = 0; hf < 2; hf++) {
                mx0 = fmaxf(mx0, fmaxf(sacc[ig][hf][0], sacc[ig][hf][1]));
                mx1 = fmaxf(mx1, fmaxf(sacc[ig][hf][2], sacc[ig][hf][3]));
            }
        #pragma unroll
        for (int off = 1; off <= 2; off <<= 1) {
            mx0 = fmaxf(mx0, __shfl_xor_sync(0xffffffffu, mx0, off));
            mx1 = fmaxf(mx1, __shfl_xor_sync(0xffffffffu, mx1, off));
        }
        float mn0 = fmaxf(m0, mx0), mn1 = fmaxf(m1, mx1);
        float f0 = __expf(m0 - mn0), f1 = __expf(m1 - mn1);
        float s0 = 0.f, s1 = 0.f;
        #pragma unroll
        for (int ig = 0; ig < 4; ig++)
            #pragma unroll
            for (int hf = 0; hf < 2; hf++) {
                sacc[ig][hf][0] = __expf(sacc[ig][hf][0] - mn0);
                sacc[ig][hf][1] = __expf(sacc[ig][hf][1] - mn0);
                sacc[ig][hf][2] = __expf(sacc[ig][hf][2] - mn1);
                sacc[ig][hf][3] = __expf(sacc[ig][hf][3] - mn1);
                s0 += sacc[ig][hf][0] + sacc[ig][hf][1];
                s1 += sacc[ig][hf][2] + sacc[ig][hf][3];
            }
        #pragma unroll
        for (int off = 1; off <= 2; off <<= 1) {
            s0 += __shfl_xor_sync(0xffffffffu, s0, off);
            s1 += __shfl_xor_sync(0xffffffffu, s1, off);
        }
        l0 = l0 * f0 + s0;  l1 = l1 * f1 + s1;
        m0 = mn0;           m1 = mn1;
        #pragma unroll
        for (int ig = 0; ig < 4; ig++)
            #pragma unroll
            for (int hf = 0; hf < 2; hf++) {
                oacc[ig][hf][0] *= f0; oacc[ig][hf][1] *= f0;
                oacc[ig][hf][2] *= f1; oacc[ig][hf][3] *= f1;
            }

        // ---- P -> per-warp smem ----
        {
            float* psw = sm->Ps[warp];
            int r0 = lane >> 2;
            #pragma unroll
            for (int ig = 0; ig < 4; ig++)
                #pragma unroll
                for (int hf = 0; hf < 2; hf++) {
                    int cb = ig * 16 + hf * 8 + 2 * (lane & 3);
                    float2 a; a.x = sacc[ig][hf][0]; a.y = sacc[ig][hf][1];
                    float2 b; b.x = sacc[ig][hf][2]; b.y = sacc[ig][hf][3];
                    *reinterpret_cast<float2*>(&psw[r0 * 68 + cb]) = a;
                    *reinterpret_cast<float2*>(&psw[(r0 + 8) * 68 + cb]) = b;
                }
        }
        __syncwarp();

        // ---- O += P V ----
        #pragma unroll
        for (int k8 = 0; k8 < 8; k8++) {
            uint32_t af[4];
            {
                int m = (lane & 7) + ((lane >> 3) & 1) * 8;
                uint32_t addr = psu + (uint32_t)(m * 68) * 4 + k8 * 32 + ((lane >> 4) & 1) * 16;
                ldsm4(af[0], af[1], af[2], af[3], addr);
                F2TF32(af[0]); F2TF32(af[1]); F2TF32(af[2]); F2TF32(af[3]);
            }
            #pragma unroll
            for (int ig = 0; ig < 4; ig++) {
                uint32_t bf[4];
                int n = ig * 16 + (lane & 7) + ((lane >> 4) & 1) * 8;
                uint32_t addr = vtu + (uint32_t)(n * 68) * 4 + k8 * 32 + ((lane >> 3) & 1) * 16;
                ldsm4(bf[0], bf[1], bf[2], bf[3], addr);
                F2TF32(bf[0]); F2TF32(bf[1]); F2TF32(bf[2]); F2TF32(bf[3]);
                mma_tf32(oacc[ig][0], af, bf + 0);
                mma_tf32(oacc[ig][1], af, bf + 2);
            }
        }
    }

    // ---- epilogue: O / l ----
    float inv0 = 1.f / l0, inv1 = 1.f / l1;
    long gi = (long)zb * NN_ + mt * 128 + warp * 16 + (lane >> 2);
    #pragma unroll
    for (int ig = 0; ig < 4; ig++)
        #pragma unroll
        for (int hf = 0; hf < 2; hf++) {
            int c = zh * 64 + ig * 16 + hf * 8 + 2 * (lane & 3);
            float2 a; a.x = oacc[ig][hf][0] * inv0; a.y = oacc[ig][hf][1] * inv0;
            float2 b; b.x = oacc[ig][hf][2] * inv1; b.y = oacc[ig][hf][3] * inv1;
            *reinterpret_cast<float2*>(&o[gi * DD + c]) = a;
            *reinterpret_cast<float2*>(&o[(gi + 8) * DD + c]) = b;
        }
}

// =====================================================================
// tf32 tensor-core GEMM (unchanged from round 3; BT=true path used only).
// =====================================================================
template<int BM, int BN, int WM, int WN, bool BT>
__global__ __launch_bounds__(256) void tgemm(
    const float* __restrict__ A, const float* __restrict__ B, float* __restrict__ C,
    int lda, int ldb, int ldc, int Hdim,
    long sAb, long sAh, long sBb, long sBh, long sCb, long sCh,
    int K, float alpha,
    const float* __restrict__ bias, float biasSign, long sBiasB, long sBiasH,
    const float* __restrict__ residual)
{
    constexpr int BK = 16;
    constexpr int LDS_ = 20;
    constexpr int WARPS_N = BN / WN;
    constexpr int MF = WM / 16;
    constexpr int NG = WN / 16;
    constexpr int AF4 = BM * BK / 1024;
    constexpr int BF4 = BN * BK / 1024;
    constexpr uint32_t ASZ = BM * LDS_ * 4;
    constexpr uint32_t BSZ = BN * LDS_ * 4;

    __shared__ float As[2][BM * LDS_];
    __shared__ float Bs[2][BN * LDS_];

    const int tid  = threadIdx.x;
    const int lane = tid & 31;
    const int warp = tid >> 5;
    const int wm = warp / WARPS_N;
    const int wn = warp % WARPS_N;

    const int z  = blockIdx.z;
    const int zb = z / Hdim, zh = z % Hdim;
    A += zb * sAb + zh * sAh;
    B += zb * sBb + zh * sBh;
    C += zb * sCb + zh * sCh;
    const float* biasp = bias ? (bias + zb * sBiasB + zh * sBiasH) : nullptr;

    const int row0 = blockIdx.y * BM;
    const int col0 = blockIdx.x * BN;

    const uint32_t asu = (uint32_t)__cvta_generic_to_shared(&As[0][0]);
    const uint32_t bsu = (uint32_t)__cvta_generic_to_shared(&Bs[0][0]);

    float acc[MF][NG * 2][4];
    #pragma unroll
    for (int i = 0; i < MF; i++)
        #pragma unroll
        for (int j = 0; j < NG * 2; j++)
            #pragma unroll
            for (int q = 0; q < 4; q++) acc[i][j][q] = 0.f;

    const int KT = K / BK;

    auto prefetch = [&](int s, int kt) {
        const float* Ag = A + (long)row0 * lda + kt * BK;
        #pragma unroll
        for (int i = 0; i < AF4; i++) {
            int l = tid + 256 * i;
            int r = l >> 2, c = (l & 3) << 2;
            CP_ASYNC16(asu + (uint32_t)s * ASZ + (uint32_t)(r * LDS_ + c) * 4,
                       Ag + (long)r * lda + c);
        }
        const float* Bg = B + (long)col0 * ldb + kt * BK;
        #pragma unroll
        for (int i = 0; i < BF4; i++) {
            int l = tid + 256 * i;
            int r = l >> 2, c = (l & 3) << 2;
            CP_ASYNC16(bsu + (uint32_t)s * BSZ + (uint32_t)(r * LDS_ + c) * 4,
                       Bg + (long)r * ldb + c);
        }
        CP_COMMIT();
    };

    prefetch(0, 0);

    for (int kt = 0; kt < KT; kt++) {
        if (kt + 1 < KT) { prefetch((kt + 1) & 1, kt + 1); CP_WAIT1(); }
        else             { CP_WAIT0(); }
        __syncthreads();

        const uint32_t ab = asu + (uint32_t)(kt & 1) * ASZ;
        const uint32_t bb = bsu + (uint32_t)(kt & 1) * BSZ;

        #pragma unroll
        for (int k8 = 0; k8 < 2; k8++) {
            uint32_t af[MF][4];
            #pragma unroll
            for (int im = 0; im < MF; im++) {
                int m = wm * WM + im * 16 + (lane & 7) + ((lane >> 3) & 1) * 8;
                uint32_t addr = ab + (uint32_t)(m * LDS_) * 4 + k8 * 32 + ((lane >> 4) & 1) * 16;
                ldsm4(af[im][0], af[im][1], af[im][2], af[im][3], addr);
                F2TF32(af[im][0]); F2TF32(af[im][1]); F2TF32(af[im][2]); F2TF32(af[im][3]);
            }
            #pragma unroll
            for (int ig = 0; ig < NG; ig++) {
                uint32_t bf[4];
                int n = wn * WN + ig * 16 + (lane & 7) + ((lane >> 4) & 1) * 8;
                uint32_t addr = bb + (uint32_t)(n * LDS_) * 4 + k8 * 32 + ((lane >> 3) & 1) * 16;
                ldsm4(bf[0], bf[1], bf[2], bf[3], addr);
                F2TF32(bf[0]); F2TF32(bf[1]); F2TF32(bf[2]); F2TF32(bf[3]);
                #pragma unroll
                for (int im = 0; im < MF; im++) {
                    mma_tf32(acc[im][ig * 2 + 0], af[im], bf + 0);
                    mma_tf32(acc[im][ig * 2 + 1], af[im], bf + 2);
                }
            }
        }
        __syncthreads();
    }

    #pragma unroll
    for (int im = 0; im < MF; im++) {
        int mrow = row0 + wm * WM + im * 16 + (lane >> 2);
        #pragma unroll
        for (int jg = 0; jg < NG * 2; jg++) {
            int ncol = col0 + wn * WN + (jg >> 1) * 16 + (jg & 1) * 8 + 2 * (lane & 3);
            float b0 = 0.f, b1 = 0.f;
            if (biasp) { b0 = biasSign * biasp[ncol]; b1 = biasSign * biasp[ncol + 1]; }
            #pragma unroll
            for (int half = 0; half < 2; half++) {
                long r = mrow + half * 8;
                float v0 = alpha * acc[im][jg][half * 2 + 0] + b0;
                float v1 = alpha * acc[im][jg][half * 2 + 1] + b1;
                if (residual) {
                    v0 += residual[r * ldc + ncol];
                    v1 += residual[r * ldc + ncol + 1];
                }
                float2 vv; vv.x = v0; vv.y = v1;
                *reinterpret_cast<float2*>(&C[r * ldc + ncol]) = vv;
            }
        }
    }
}

// ---------------- launch ----------------
extern "C" void kernel_launch(void* const* d_in, const int* in_sizes, int n_in,
                              void* d_out, int out_size)
{
    const float* x      = (const float*)d_in[0];
    const float* coords = (const float*)d_in[1];
    const float* ln1_g  = (const float*)d_in[2];
    const float* ln1_b  = (const float*)d_in[3];
    const float* qkv_w  = (const float*)d_in[4];
    const float* qkv_b  = (const float*)d_in[5];
    const float* rel_w  = (const float*)d_in[6];
    const float* ln2_g  = (const float*)d_in[7];
    const float* ln2_b  = (const float*)d_in[8];
    const float* win_w  = (const float*)d_in[9];
    const float* win_b  = (const float*)d_in[10];
    const float* wout_w = (const float*)d_in[11];
    const float* wout_b = (const float*)d_in[12];
    float* out = (float*)d_out;

    float* S = nullptr;
    cudaGetSymbolAddress((void**)&S, g_scratch);
    float* p   = S + OFF_P;
    float* xm  = S + OFF_XM;
    float* ho  = S + OFF_HO;             // h, then o
    float* qkv = S + OFF_QKV;
    float* h2  = S + OFF_QKV;            // reuses qkv region after attention
    float* uv  = S + OFF_SC;
    float* act = S + OFF_SC + 16777216L;

    static bool attr_set = false;
    if (!attr_set) {
        cudaFuncSetAttribute(fa_kernel, cudaFuncAttributeMaxDynamicSharedMemorySize,
                             (int)FA_SMEM_BYTES);
        attr_set = true;
    }

    // 1) h = LN1(x)
    ln_kernel<<<ROWS, 256>>>(x, nullptr, ln1_g, ln1_b, ho, nullptr);

    // 2) qkv = h @ qkv_w^T + qkv_b
    tgemm<128,128,64,32,true><<<dim3(D3/128, ROWS/128, 1), 256>>>(
        ho, qkv_w, qkv, DD, DD, D3, 1,
        0,0, 0,0, 0,0,
        DD, 1.f, qkv_b, 1.f, 0, 0, nullptr);

    // 3) p[b,h,n]
    p_kernel<<<(ZHN*NN_)/256, 256>>>(coords, rel_w, p);

    // 4-6) fused attention -> o (into ho)
    fa_kernel<<<dim3(8, ZHN), 256, FA_SMEM_BYTES>>>(qkv, p, ho);

    // 7) xm = x + o ; h2 = LN2(xm)
    ln_kernel<<<ROWS, 256>>>(x, ho, ln2_g, ln2_b, h2, xm);

    // 8) uv = h2 @ win_w^T + win_b
    tgemm<128,128,64,32,true><<<dim3((2*HID)/128, ROWS/128, 1), 256>>>(
        h2, win_w, uv, DD, DD, 2*HID, 1,
        0,0, 0,0, 0,0,
        DD, 1.f, win_b, 1.f, 0, 0, nullptr);

    // 9) act = silu(u) * g
    swiglu_kernel<<<(ROWS*HID)/256, 256>>>(uv, act);

    // 10) out = act @ wout_w^T + wout_b + xm
    tgemm<128,128,64,32,true><<<dim3(DD/128, ROWS/128, 1), 256>>>(
        act, wout_w, out, HID, HID, DD, 1,
        0,0, 0,0, 0,0,
        HID, 1.f, wout_b, 1.f, 0, 0, xm);
}

// round 7
// speedup vs baseline: 9.8558x; 2.0500x over previous
#include <cuda_runtime.h>
#include <cuda_bf16.h>
#include <math.h>
#include <stdint.h>

// ---------------- problem constants ----------------
#define BB   4
#define NN_  1024
#define DD   768
#define HH   12
#define DH   64
#define HID  2048
#define D3   2304          // 3*D
#define ROWS (BB*NN_)      // 4096
#define ZHN  (BB*HH)       // 48

// ---------------- scratch (floats; bf16 regions aliased, all 16B aligned) ----------------
#define OFF_P      0L          // fp32  48K
#define OFF_XM     49152L      // fp32  3.1M
#define OFF_O      3194880L    // fp32  3.1M
#define OFF_QKVBF  6340608L    // bf16  9.4M elems (4718592 floats)
#define OFF_HBF    11059200L   // bf16  3.1M elems (h, then h2)
#define OFF_WQ     12632064L   // bf16  qkv_w
#define OFF_WI     13516800L   // bf16  win_w
#define OFF_WO     15089664L   // bf16  wout_w
#define OFF_UV     15876096L   // fp32  16.7M
#define OFF_ACTBF  32653312L   // bf16  8.4M elems
#define SCRATCH_TOTAL 36847616L   // ~147 MB

__device__ float g_scratch[SCRATCH_TOTAL];

// ---------------- PTX helpers ----------------
#define CP_ASYNC16(dst, src) asm volatile("cp.async.cg.shared.global [%0], [%1], 16;\n" :: "r"(dst), "l"(src))
#define CP_COMMIT()  asm volatile("cp.async.commit_group;\n")
#define CP_WAIT1()   asm volatile("cp.async.wait_group 1;\n" ::: "memory")
#define CP_WAIT0()   asm volatile("cp.async.wait_group 0;\n" ::: "memory")

__device__ __forceinline__ void ldsm4(uint32_t& r0, uint32_t& r1, uint32_t& r2, uint32_t& r3, uint32_t addr) {
    asm volatile("ldmatrix.sync.aligned.m8n8.x4.shared.b16 {%0,%1,%2,%3}, [%4];\n"
                 : "=r"(r0), "=r"(r1), "=r"(r2), "=r"(r3) : "r"(addr));
}
__device__ __forceinline__ void ldsm4t(uint32_t& r0, uint32_t& r1, uint32_t& r2, uint32_t& r3, uint32_t addr) {
    asm volatile("ldmatrix.sync.aligned.m8n8.x4.trans.shared.b16 {%0,%1,%2,%3}, [%4];\n"
                 : "=r"(r0), "=r"(r1), "=r"(r2), "=r"(r3) : "r"(addr));
}
__device__ __forceinline__ void mma_bf16(float* c, const uint32_t* a, const uint32_t* b) {
    asm volatile(
        "mma.sync.aligned.m16n8k16.row.col.f32.bf16.bf16.f32 "
        "{%0,%1,%2,%3},{%4,%5,%6,%7},{%8,%9},{%0,%1,%2,%3};\n"
        : "+f"(c[0]), "+f"(c[1]), "+f"(c[2]), "+f"(c[3])
        : "r"(a[0]), "r"(a[1]), "r"(a[2]), "r"(a[3]), "r"(b[0]), "r"(b[1]));
}

// ---------------- fp32 -> bf16 convert ----------------
__global__ void cvt_kernel(const float* __restrict__ in, __nv_bfloat16* __restrict__ out, int n)
{
    int i = (blockIdx.x * 256 + threadIdx.x) * 4;
    if (i >= n) return;
    float4 v = *reinterpret_cast<const float4*>(in + i);
    *reinterpret_cast<__nv_bfloat162*>(out + i)     = __floats2bfloat162_rn(v.x, v.y);
    *reinterpret_cast<__nv_bfloat162*>(out + i + 2) = __floats2bfloat162_rn(v.z, v.w);
}

// ---------------- block reduce ----------------
__device__ __forceinline__ float blk_reduce(float v, float* sm, int op) {
    __syncthreads();
    #pragma unroll
    for (int o = 16; o > 0; o >>= 1) {
        float t = __shfl_xor_sync(0xffffffffu, v, o);
        v = op ? fmaxf(v, t) : (v + t);
    }
    int lane = threadIdx.x & 31, w = threadIdx.x >> 5;
    if (lane == 0) sm[w] = v;
    __syncthreads();
    float r = sm[0];
    #pragma unroll
    for (int i = 1; i < 8; i++) r = op ? fmaxf(r, sm[i]) : (r + sm[i]);
    return r;
}

// ---------------- LayerNorm -> bf16 out (optional fp32 residual-sum out) ----------------
__global__ __launch_bounds__(256) void ln_kernel(
    const float* __restrict__ x, const float* __restrict__ res,
    const float* __restrict__ g, const float* __restrict__ b,
    __nv_bfloat16* __restrict__ out, float* __restrict__ sum_out)
{
    __shared__ float sm[32];
    long row = blockIdx.x;
    int t = threadIdx.x;
    const float* xr = x + row * DD;
    float v[3];
    float s = 0.f;
    #pragma unroll
    for (int i = 0; i < 3; i++) {
        int idx = t + i * 256;
        float val = xr[idx];
        if (res) val += res[row * DD + idx];
        v[i] = val; s += val;
    }
    float mean = blk_reduce(s, sm, 0) * (1.f / 768.f);
    float vs = 0.f;
    #pragma unroll
    for (int i = 0; i < 3; i++) { float d = v[i] - mean; vs += d * d; }
    float var = blk_reduce(vs, sm, 0) * (1.f / 768.f);
    float rstd = rsqrtf(var + 1e-5f);
    #pragma unroll
    for (int i = 0; i < 3; i++) {
        int idx = t + i * 256;
        if (sum_out) sum_out[row * DD + idx] = v[i];
        out[row * DD + idx] = __float2bfloat16_rn((v[i] - mean) * rstd * g[idx] + b[idx]);
    }
}

// ---------------- p[b,h,n] ----------------
__global__ void p_kernel(const float* __restrict__ coords,
                         const float* __restrict__ rel_w,
                         float* __restrict__ p)
{
    int idx = blockIdx.x * 256 + threadIdx.x;
    if (idx >= ZHN * NN_) return;
    int n = idx & (NN_ - 1);
    int h = (idx >> 10) % HH;
    int b = idx / (HH * NN_);
    const float* c = coords + ((long)b * NN_ + n) * 3;
    const float* w = rel_w + h * 3;
    p[idx] = c[0] * w[0] + c[1] * w[1] + c[2] * w[2];
}

// ---------------- SwiGLU -> bf16 ----------------
__global__ void swiglu_kernel(const float* __restrict__ uv, __nv_bfloat16* __restrict__ act)
{
    long idx = (long)blockIdx.x * 256 + threadIdx.x;
    long m = idx >> 11;
    int  j = (int)(idx & 2047);
    float u  = uv[m * 4096 + j];
    float gg = uv[m * 4096 + 2048 + j];
    float sig = 1.f / (1.f + __expf(-u));
    act[idx] = __float2bfloat16_rn(u * sig * gg);
}

// =====================================================================
// bf16 tensor-core GEMM: C = A(MxK) * B^T (B is NxK row-major) + bias [+ res]
// BM=BN=128, BK=32, 8 warps of 64x32. OBF: write bf16, else fp32.
// Smem row stride 40 bf16 (80B) -> conflict-free ldmatrix.
// =====================================================================
template<bool OBF>
__global__ __launch_bounds__(256) void tgemm(
    const __nv_bfloat16* __restrict__ A, const __nv_bfloat16* __restrict__ B,
    void* __restrict__ Cv,
    int lda, int ldb, int ldc, int K,
    const float* __restrict__ bias, const float* __restrict__ residual)
{
    constexpr int LDSB = 40;                    // bf16 elems per smem row
    constexpr uint32_t STG = 128 * LDSB * 2;    // stage bytes

    __shared__ __nv_bfloat16 As[2][128 * LDSB];
    __shared__ __nv_bfloat16 Bs[2][128 * LDSB];

    const int tid  = threadIdx.x;
    const int lane = tid & 31;
    const int warp = tid >> 5;
    const int wm = warp >> 2;        // 0..1
    const int wn = warp & 3;         // 0..3

    const int row0 = blockIdx.y * 128;
    const int col0 = blockIdx.x * 128;

    const uint32_t asu = (uint32_t)__cvta_generic_to_shared(&As[0][0]);
    const uint32_t bsu = (uint32_t)__cvta_generic_to_shared(&Bs[0][0]);

    float acc[4][4][4];
    #pragma unroll
    for (int i = 0; i < 4; i++)
        #pragma unroll
        for (int j = 0; j < 4; j++)
            #pragma unroll
            for (int q = 0; q < 4; q++) acc[i][j][q] = 0.f;

    const int KT = K / 32;

    auto prefetch = [&](int s, int kt) {
        const __nv_bfloat16* Ag = A + (long)row0 * lda + kt * 32;
        const __nv_bfloat16* Bg = B + (long)col0 * ldb + kt * 32;
        #pragma unroll
        for (int i = 0; i < 2; i++) {
            int l = tid + 256 * i;
            int r = l >> 2, c = (l & 3) << 3;
            CP_ASYNC16(asu + s * STG + (uint32_t)(r * LDSB + c) * 2, Ag + (long)r * lda + c);
            CP_ASYNC16(bsu + s * STG + (uint32_t)(r * LDSB + c) * 2, Bg + (long)r * ldb + c);
        }
        CP_COMMIT();
    };

    prefetch(0, 0);

    for (int kt = 0; kt < KT; kt++) {
        if (kt + 1 < KT) { prefetch((kt + 1) & 1, kt + 1); CP_WAIT1(); }
        else             { CP_WAIT0(); }
        __syncthreads();

        const uint32_t ab = asu + (uint32_t)(kt & 1) * STG;
        const uint32_t bb = bsu + (uint32_t)(kt & 1) * STG;

        #pragma unroll
        for (int k16 = 0; k16 < 2; k16++) {
            uint32_t af[4][4];
            #pragma unroll
            for (int im = 0; im < 4; im++) {
                int m = wm * 64 + im * 16 + (lane & 15);
                uint32_t addr = ab + (uint32_t)m * (LDSB * 2) + k16 * 32 + ((lane >> 4) & 1) * 16;
                ldsm4(af[im][0], af[im][1], af[im][2], af[im][3], addr);
            }
            #pragma unroll
            for (int ig = 0; ig < 2; ig++) {
                uint32_t bf[4];
                int n = wn * 32 + ig * 16 + (lane & 7) + ((lane >> 4) & 1) * 8;
                uint32_t addr = bb + (uint32_t)n * (LDSB * 2) + k16 * 32 + ((lane >> 3) & 1) * 16;
                ldsm4(bf[0], bf[1], bf[2], bf[3], addr);
                #pragma unroll
                for (int im = 0; im < 4; im++) {
                    mma_bf16(acc[im][ig * 2 + 0], af[im], bf + 0);
                    mma_bf16(acc[im][ig * 2 + 1], af[im], bf + 2);
                }
            }
        }
        __syncthreads();
    }

    // ---- epilogue ----
    #pragma unroll
    for (int im = 0; im < 4; im++) {
        int mrow = row0 + wm * 64 + im * 16 + (lane >> 2);
        #pragma unroll
        for (int jg = 0; jg < 4; jg++) {
            int ncol = col0 + wn * 32 + (jg >> 1) * 16 + (jg & 1) * 8 + 2 * (lane & 3);
            float b0 = 0.f, b1 = 0.f;
            if (bias) { b0 = bias[ncol]; b1 = bias[ncol + 1]; }
            #pragma unroll
            for (int half = 0; half < 2; half++) {
                long r = mrow + half * 8;
                float v0 = acc[im][jg][half * 2 + 0] + b0;
                float v1 = acc[im][jg][half * 2 + 1] + b1;
                if (residual) {
                    v0 += residual[r * ldc + ncol];
                    v1 += residual[r * ldc + ncol + 1];
                }
                if (OBF) {
                    __nv_bfloat16* C = (__nv_bfloat16*)Cv;
                    *reinterpret_cast<__nv_bfloat162*>(&C[r * ldc + ncol]) =
                        __floats2bfloat162_rn(v0, v1);
                } else {
                    float* C = (float*)Cv;
                    float2 vv; vv.x = v0; vv.y = v1;
                    *reinterpret_cast<float2*>(&C[r * ldc + ncol]) = vv;
                }
            }
        }
    }
}

// =====================================================================
// Fused flash attention, bf16 MMA. Block = (m-tile of 128 q-rows, z=b*H+h).
// 8 warps x 16 q-rows. 16 KV tiles of 64 keys, double-buffered cp.async.
// V consumed via ldmatrix.trans (no explicit transpose stage).
// =====================================================================
struct FaSmem {
    __nv_bfloat16 Qs[128 * 72];
    __nv_bfloat16 Ks[2][64 * 72];
    __nv_bfloat16 Vs[2][64 * 72];
    __nv_bfloat16 Ps[8][16 * 72];
    float psc[2][64];
};
#define FA_SMEM_BYTES (sizeof(FaSmem))

__global__ __launch_bounds__(256, 2) void fa_kernel(
    const __nv_bfloat16* __restrict__ qkv, const float* __restrict__ p,
    float* __restrict__ o)
{
    extern __shared__ float smf[];
    FaSmem* sm = reinterpret_cast<FaSmem*>(smf);
    const int tid = threadIdx.x, lane = tid & 31, warp = tid >> 5;
    const int mt = blockIdx.x;       // 0..7
    const int z  = blockIdx.y;       // 0..47
    const int zb = z / HH, zh = z % HH;

    const __nv_bfloat16* Qg = qkv + ((long)zb * NN_ + mt * 128) * D3 + zh * 64;
    const __nv_bfloat16* Kg = qkv + (long)zb * NN_ * D3 + DD + zh * 64;
    const __nv_bfloat16* Vg = qkv + (long)zb * NN_ * D3 + 2 * DD + zh * 64;
    const float* pg = p + (long)z * NN_;

    const uint32_t qsu  = (uint32_t)__cvta_generic_to_shared(sm->Qs);
    const uint32_t ksu  = (uint32_t)__cvta_generic_to_shared(sm->Ks[0]);
    const uint32_t vsu  = (uint32_t)__cvta_generic_to_shared(sm->Vs[0]);
    const uint32_t psu  = (uint32_t)__cvta_generic_to_shared(sm->Ps[warp]);
    const uint32_t pscu = (uint32_t)__cvta_generic_to_shared(sm->psc[0]);
    constexpr uint32_t KVB = 64 * 72 * 2;   // one KV stage bytes

    auto prep = [&](int s, int j) {
        #pragma unroll
        for (int i = 0; i < 2; i++) {
            int l = tid + 256 * i;
            int r = l >> 3, c = (l & 7) << 3;
            CP_ASYNC16(ksu + (uint32_t)s * KVB + (uint32_t)(r * 72 + c) * 2,
                       Kg + (long)(j * 64 + r) * D3 + c);
            CP_ASYNC16(vsu + (uint32_t)s * KVB + (uint32_t)(r * 72 + c) * 2,
                       Vg + (long)(j * 64 + r) * D3 + c);
        }
        if (tid < 16)
            CP_ASYNC16(pscu + (uint32_t)s * 256 + tid * 16, pg + j * 64 + tid * 4);
        CP_COMMIT();
    };

    // Q load (joins group 0 with prep(0,0))
    #pragma unroll
    for (int i = 0; i < 4; i++) {
        int l = tid + 256 * i;
        int r = l >> 3, c = (l & 7) << 3;
        CP_ASYNC16(qsu + (uint32_t)(r * 72 + c) * 2, Qg + (long)r * D3 + c);
    }
    prep(0, 0);

    float m0 = -1e30f, m1 = -1e30f, l0 = 0.f, l1 = 0.f;
    float oacc[4][2][4];
    #pragma unroll
    for (int a = 0; a < 4; a++)
        #pragma unroll
        for (int b = 0; b < 2; b++)
            #pragma unroll
            for (int q = 0; q < 4; q++) oacc[a][b][q] = 0.f;

    for (int j = 0; j < 16; j++) {
        const int s = j & 1;
        __syncthreads();                       // prev compute done: stage s^1 free
        if (j < 15) { prep(s ^ 1, j + 1); CP_WAIT1(); }
        else        { CP_WAIT0(); }
        __syncthreads();                       // stage s visible

        // ---- S = Q K^T ----
        float sacc[4][2][4];
        #pragma unroll
        for (int a = 0; a < 4; a++)
            #pragma unroll
            for (int b = 0; b < 2; b++)
                #pragma unroll
                for (int q = 0; q < 4; q++) sacc[a][b][q] = 0.f;

        const uint32_t ksb = ksu + (uint32_t)s * KVB;
        #pragma unroll
        for (int k16 = 0; k16 < 4; k16++) {
            uint32_t af[4];
            {
                int m = warp * 16 + (lane & 15);
                uint32_t addr = qsu + (uint32_t)m * 144 + k16 * 32 + ((lane >> 4) & 1) * 16;
                ldsm4(af[0], af[1], af[2], af[3], addr);
            }
            #pragma unroll
            for (int ig = 0; ig < 4; ig++) {
                uint32_t bf[4];
                int n = ig * 16 + (lane & 7) + ((lane >> 4) & 1) * 8;
                uint32_t addr = ksb + (uint32_t)n * 144 + k16 * 32 + ((lane >> 3) & 1) * 16;
                ldsm4(bf[0], bf[1], bf[2], bf[3], addr);
                mma_bf16(sacc[ig][0], af, bf + 0);
                mma_bf16(sacc[ig][1], af, bf + 2);
            }
        }

        // ---- scale + key bias ----
        #pragma unroll
        for (int ig = 0; ig < 4; ig++)
            #pragma unroll
            for (int hf = 0; hf < 2; hf++) {
                int cb = ig * 16 + hf * 8 + 2 * (lane & 3);
                float p0 = sm->psc[s][cb], p1 = sm->psc[s][cb + 1];
                sacc[ig][hf][0] = sacc[ig][hf][0] * 0.125f - p0;
                sacc[ig][hf][1] = sacc[ig][hf][1] * 0.125f - p1;
                sacc[ig][hf][2] = sacc[ig][hf][2] * 0.125f - p0;
                sacc[ig][hf][3] = sacc[ig][hf][3] * 0.125f - p1;
            }

        // ---- online softmax ----
        float mx0 = -1e30f, mx1 = -1e30f;
        #pragma unroll
        for (int ig = 0; ig < 4; ig++)
            #pragma unroll
            for (int hf = 0; hf < 2; hf++) {
                mx0 = fmaxf(mx0, fmaxf(sacc[ig][hf][0], sacc[ig][hf][1]));
                mx1 = fmaxf(mx1, fmaxf(sacc[ig][hf][2], sacc[ig][hf][3]));
            }
        #pragma unroll
        for (int off = 1; off <= 2; off <<= 1) {
            mx0 = fmaxf(mx0, __shfl_xor_sync(0xffffffffu, mx0, off));
            mx1 = fmaxf(mx1, __shfl_xor_sync(0xffffffffu, mx1, off));
        }
        float mn0 = fmaxf(m0, mx0), mn1 = fmaxf(m1, mx1);
        float f0 = __expf(m0 - mn0), f1 = __expf(m1 - mn1);
        float s0 = 0.f, s1 = 0.f;
        #pragma unroll
        for (int ig = 0; ig < 4; ig++)
            #pragma unroll
            for (int hf = 0; hf < 2; hf++) {
                sacc[ig][hf][0] = __expf(sacc[ig][hf][0] - mn0);
                sacc[ig][hf][1] = __expf(sacc[ig][hf][1] - mn0);
                sacc[ig][hf][2] = __expf(sacc[ig][hf][2] - mn1);
                sacc[ig][hf][3] = __expf(sacc[ig][hf][3] - mn1);
                s0 += sacc[ig][hf][0] + sacc[ig][hf][1];
                s1 += sacc[ig][hf][2] + sacc[ig][hf][3];
            }
        #pragma unroll
        for (int off = 1; off <= 2; off <<= 1) {
            s0 += __shfl_xor_sync(0xffffffffu, s0, off);
            s1 += __shfl_xor_sync(0xffffffffu, s1, off);
        }
        l0 = l0 * f0 + s0;  l1 = l1 * f1 + s1;
        m0 = mn0;           m1 = mn1;
        #pragma unroll
        for (int ig = 0; ig < 4; ig++)
            #pragma unroll
            for (int hf = 0; hf < 2; hf++) {
                oacc[ig][hf][0] *= f0; oacc[ig][hf][1] *= f0;
                oacc[ig][hf][2] *= f1; oacc[ig][hf][3] *= f1;
            }

        // ---- P -> per-warp smem (bf16) ----
        {
            __nv_bfloat16* psw = sm->Ps[warp];
            int r0 = lane >> 2;
            #pragma unroll
            for (int ig = 0; ig < 4; ig++)
                #pragma unroll
                for (int hf = 0; hf < 2; hf++) {
                    int cb = ig * 16 + hf * 8 + 2 * (lane & 3);
                    *reinterpret_cast<__nv_bfloat162*>(&psw[r0 * 72 + cb]) =
                        __floats2bfloat162_rn(sacc[ig][hf][0], sacc[ig][hf][1]);
                    *reinterpret_cast<__nv_bfloat162*>(&psw[(r0 + 8) * 72 + cb]) =
                        __floats2bfloat162_rn(sacc[ig][hf][2], sacc[ig][hf][3]);
                }
        }
        __syncwarp();

        // ---- O += P V  (V via trans-ldmatrix from [key][d]) ----
        const uint32_t vsb = vsu + (uint32_t)s * KVB;
        #pragma unroll
        for (int k16 = 0; k16 < 4; k16++) {
            uint32_t af[4];
            {
                int m = lane & 15;
                uint32_t addr = psu + (uint32_t)m * 144 + k16 * 32 + ((lane >> 4) & 1) * 16;
                ldsm4(af[0], af[1], af[2], af[3], addr);
            }
            #pragma unroll
            for (int ig = 0; ig < 4; ig++) {
                uint32_t bf[4];
                int key = k16 * 16 + ((lane >> 3) & 1) * 8 + (lane & 7);
                uint32_t addr = vsb + (uint32_t)key * 144 + ig * 32 + ((lane >> 4) & 1) * 16;
                ldsm4t(bf[0], bf[1], bf[2], bf[3], addr);
                mma_bf16(oacc[ig][0], af, bf + 0);
                mma_bf16(oacc[ig][1], af, bf + 2);
            }
        }
    }

    // ---- epilogue: O / l ----
    float inv0 = 1.f / l0, inv1 = 1.f / l1;
    long gi = (long)zb * NN_ + mt * 128 + warp * 16 + (lane >> 2);
    #pragma unroll
    for (int ig = 0; ig < 4; ig++)
        #pragma unroll
        for (int hf = 0; hf < 2; hf++) {
            int c = zh * 64 + ig * 16 + hf * 8 + 2 * (lane & 3);
            float2 a; a.x = oacc[ig][hf][0] * inv0; a.y = oacc[ig][hf][1] * inv0;
            float2 b; b.x = oacc[ig][hf][2] * inv1; b.y = oacc[ig][hf][3] * inv1;
            *reinterpret_cast<float2*>(&o[gi * DD + c]) = a;
            *reinterpret_cast<float2*>(&o[(gi + 8) * DD + c]) = b;
        }
}

// ---------------- launch ----------------
extern "C" void kernel_launch(void* const* d_in, const int* in_sizes, int n_in,
                              void* d_out, int out_size)
{
    const float* x      = (const float*)d_in[0];
    const float* coords = (const float*)d_in[1];
    const float* ln1_g  = (const float*)d_in[2];
    const float* ln1_b  = (const float*)d_in[3];
    const float* qkv_w  = (const float*)d_in[4];
    const float* qkv_b  = (const float*)d_in[5];
    const float* rel_w  = (const float*)d_in[6];
    const float* ln2_g  = (const float*)d_in[7];
    const float* ln2_b  = (const float*)d_in[8];
    const float* win_w  = (const float*)d_in[9];
    const float* win_b  = (const float*)d_in[10];
    const float* wout_w = (const float*)d_in[11];
    const float* wout_b = (const float*)d_in[12];
    float* out = (float*)d_out;

    float* S = nullptr;
    cudaGetSymbolAddress((void**)&S, g_scratch);
    float* p   = S + OFF_P;
    float* xm  = S + OFF_XM;
    float* o   = S + OFF_O;
    float* uv  = S + OFF_UV;
    __nv_bfloat16* qkvbf = (__nv_bfloat16*)(S + OFF_QKVBF);
    __nv_bfloat16* hbf   = (__nv_bfloat16*)(S + OFF_HBF);    // h, then h2
    __nv_bfloat16* wqbf  = (__nv_bfloat16*)(S + OFF_WQ);
    __nv_bfloat16* wibf  = (__nv_bfloat16*)(S + OFF_WI);
    __nv_bfloat16* wobf  = (__nv_bfloat16*)(S + OFF_WO);
    __nv_bfloat16* actbf = (__nv_bfloat16*)(S + OFF_ACTBF);

    cudaFuncSetAttribute(fa_kernel, cudaFuncAttributeMaxDynamicSharedMemorySize,
                         (int)FA_SMEM_BYTES);

    // 0) weight converts
    cvt_kernel<<<(D3*DD)/1024, 256>>>(qkv_w, wqbf, D3*DD);
    cvt_kernel<<<(2*HID*DD)/1024, 256>>>(win_w, wibf, 2*HID*DD);
    cvt_kernel<<<(DD*HID)/1024, 256>>>(wout_w, wobf, DD*HID);

    // 1) h = LN1(x) -> bf16
    ln_kernel<<<ROWS, 256>>>(x, nullptr, ln1_g, ln1_b, hbf, nullptr);

    // 2) qkv = h @ qkv_w^T + qkv_b -> bf16
    tgemm<true><<<dim3(D3/128, ROWS/128), 256>>>(
        hbf, wqbf, qkvbf, DD, DD, D3, DD, qkv_b, nullptr);

    // 3) p[b,h,n]
    p_kernel<<<(ZHN*NN_)/256, 256>>>(coords, rel_w, p);

    // 4-6) fused attention -> o (fp32)
    fa_kernel<<<dim3(8, ZHN), 256, FA_SMEM_BYTES>>>(qkvbf, p, o);

    // 7) xm = x + o ; h2 = LN2(xm) -> bf16
    ln_kernel<<<ROWS, 256>>>(x, o, ln2_g, ln2_b, hbf, xm);

    // 8) uv = h2 @ win_w^T + win_b -> fp32
    tgemm<false><<<dim3((2*HID)/128, ROWS/128), 256>>>(
        hbf, wibf, uv, DD, DD, 2*HID, DD, win_b, nullptr);

    // 9) act = silu(u) * g -> bf16
    swiglu_kernel<<<(ROWS*HID)/256, 256>>>(uv, actbf);

    // 10) out = act @ wout_w^T + wout_b + xm -> fp32
    tgemm<false><<<dim3(DD/128, ROWS/128), 256>>>(
        actbf, wobf, out, HID, HID, DD, HID, wout_b, xm);
}

// round 8
// speedup vs baseline: 10.8318x; 1.0990x over previous
#include <cuda_runtime.h>
#include <cuda_bf16.h>
#include <math.h>
#include <stdint.h>

// ---------------- problem constants ----------------
#define BB   4
#define NN_  1024
#define DD   768
#define HH   12
#define DH   64
#define HID  2048
#define D3   2304          // 3*D
#define ROWS (BB*NN_)      // 4096
#define ZHN  (BB*HH)       // 48

// ---------------- scratch (floats; bf16 regions aliased, all 16B aligned) ----------------
#define OFF_P      0L          // fp32  48K
#define OFF_XM     49152L      // fp32  3.1M
#define OFF_O      3194880L    // fp32  3.1M
#define OFF_QKVBF  6340608L    // bf16  9.4M elems
#define OFF_HBF    11059200L   // bf16  3.1M elems (h, then h2)
#define OFF_WQ     12632064L   // bf16  qkv_w
#define OFF_WI     13516800L   // bf16  win_w
#define OFF_WO     15089664L   // bf16  wout_w
#define OFF_ACTBF  15876096L   // bf16  8.4M elems
#define SCRATCH_TOTAL 20070400L   // ~80 MB

__device__ float g_scratch[SCRATCH_TOTAL];

// ---------------- PTX helpers ----------------
#define CP_ASYNC16(dst, src) asm volatile("cp.async.cg.shared.global [%0], [%1], 16;\n" :: "r"(dst), "l"(src))
#define CP_COMMIT()  asm volatile("cp.async.commit_group;\n")
#define CP_WAIT1()   asm volatile("cp.async.wait_group 1;\n" ::: "memory")
#define CP_WAIT0()   asm volatile("cp.async.wait_group 0;\n" ::: "memory")

__device__ __forceinline__ void ldsm4(uint32_t& r0, uint32_t& r1, uint32_t& r2, uint32_t& r3, uint32_t addr) {
    asm volatile("ldmatrix.sync.aligned.m8n8.x4.shared.b16 {%0,%1,%2,%3}, [%4];\n"
                 : "=r"(r0), "=r"(r1), "=r"(r2), "=r"(r3) : "r"(addr));
}
__device__ __forceinline__ void ldsm4t(uint32_t& r0, uint32_t& r1, uint32_t& r2, uint32_t& r3, uint32_t addr) {
    asm volatile("ldmatrix.sync.aligned.m8n8.x4.trans.shared.b16 {%0,%1,%2,%3}, [%4];\n"
                 : "=r"(r0), "=r"(r1), "=r"(r2), "=r"(r3) : "r"(addr));
}
__device__ __forceinline__ void mma_bf16(float* c, const uint32_t* a, const uint32_t* b) {
    asm volatile(
        "mma.sync.aligned.m16n8k16.row.col.f32.bf16.bf16.f32 "
        "{%0,%1,%2,%3},{%4,%5,%6,%7},{%8,%9},{%0,%1,%2,%3};\n"
        : "+f"(c[0]), "+f"(c[1]), "+f"(c[2]), "+f"(c[3])
        : "r"(a[0]), "r"(a[1]), "r"(a[2]), "r"(a[3]), "r"(b[0]), "r"(b[1]));
}

// ---------------- fp32 -> bf16 convert ----------------
__global__ void cvt_kernel(const float* __restrict__ in, __nv_bfloat16* __restrict__ out, int n)
{
    int i = (blockIdx.x * 256 + threadIdx.x) * 4;
    if (i >= n) return;
    float4 v = *reinterpret_cast<const float4*>(in + i);
    *reinterpret_cast<__nv_bfloat162*>(out + i)     = __floats2bfloat162_rn(v.x, v.y);
    *reinterpret_cast<__nv_bfloat162*>(out + i + 2) = __floats2bfloat162_rn(v.z, v.w);
}

// ---------------- block reduce ----------------
__device__ __forceinline__ float blk_reduce(float v, float* sm, int op) {
    __syncthreads();
    #pragma unroll
    for (int o = 16; o > 0; o >>= 1) {
        float t = __shfl_xor_sync(0xffffffffu, v, o);
        v = op ? fmaxf(v, t) : (v + t);
    }
    int lane = threadIdx.x & 31, w = threadIdx.x >> 5;
    if (lane == 0) sm[w] = v;
    __syncthreads();
    float r = sm[0];
    #pragma unroll
    for (int i = 1; i < 8; i++) r = op ? fmaxf(r, sm[i]) : (r + sm[i]);
    return r;
}

// ---------------- LayerNorm -> bf16 out (optional fp32 residual-sum out) ----------------
__global__ __launch_bounds__(256) void ln_kernel(
    const float* __restrict__ x, const float* __restrict__ res,
    const float* __restrict__ g, const float* __restrict__ b,
    __nv_bfloat16* __restrict__ out, float* __restrict__ sum_out)
{
    __shared__ float sm[32];
    long row = blockIdx.x;
    int t = threadIdx.x;
    const float* xr = x + row * DD;
    float v[3];
    float s = 0.f;
    #pragma unroll
    for (int i = 0; i < 3; i++) {
        int idx = t + i * 256;
        float val = xr[idx];
        if (res) val += res[row * DD + idx];
        v[i] = val; s += val;
    }
    float mean = blk_reduce(s, sm, 0) * (1.f / 768.f);
    float vs = 0.f;
    #pragma unroll
    for (int i = 0; i < 3; i++) { float d = v[i] - mean; vs += d * d; }
    float var = blk_reduce(vs, sm, 0) * (1.f / 768.f);
    float rstd = rsqrtf(var + 1e-5f);
    #pragma unroll
    for (int i = 0; i < 3; i++) {
        int idx = t + i * 256;
        if (sum_out) sum_out[row * DD + idx] = v[i];
        out[row * DD + idx] = __float2bfloat16_rn((v[i] - mean) * rstd * g[idx] + b[idx]);
    }
}

// ---------------- p[b,h,n] ----------------
__global__ void p_kernel(const float* __restrict__ coords,
                         const float* __restrict__ rel_w,
                         float* __restrict__ p)
{
    int idx = blockIdx.x * 256 + threadIdx.x;
    if (idx >= ZHN * NN_) return;
    int n = idx & (NN_ - 1);
    int h = (idx >> 10) % HH;
    int b = idx / (HH * NN_);
    const float* c = coords + ((long)b * NN_ + n) * 3;
    const float* w = rel_w + h * 3;
    p[idx] = c[0] * w[0] + c[1] * w[1] + c[2] * w[2];
}

// =====================================================================
// bf16 tensor-core GEMM: C = A(MxK) * B^T (B is NxK row-major) + bias [+ res]
// BM=BN=128, BK=32, 8 warps of 64x32. OBF: write bf16, else fp32.
// =====================================================================
template<bool OBF>
__global__ __launch_bounds__(256) void tgemm(
    const __nv_bfloat16* __restrict__ A, const __nv_bfloat16* __restrict__ B,
    void* __restrict__ Cv,
    int lda, int ldb, int ldc, int K,
    const float* __restrict__ bias, const float* __restrict__ residual)
{
    constexpr int LDSB = 40;
    constexpr uint32_t STG = 128 * LDSB * 2;

    __shared__ __nv_bfloat16 As[2][128 * LDSB];
    __shared__ __nv_bfloat16 Bs[2][128 * LDSB];

    const int tid  = threadIdx.x;
    const int lane = tid & 31;
    const int warp = tid >> 5;
    const int wm = warp >> 2;
    const int wn = warp & 3;

    const int row0 = blockIdx.y * 128;
    const int col0 = blockIdx.x * 128;

    const uint32_t asu = (uint32_t)__cvta_generic_to_shared(&As[0][0]);
    const uint32_t bsu = (uint32_t)__cvta_generic_to_shared(&Bs[0][0]);

    float acc[4][4][4];
    #pragma unroll
    for (int i = 0; i < 4; i++)
        #pragma unroll
        for (int j = 0; j < 4; j++)
            #pragma unroll
            for (int q = 0; q < 4; q++) acc[i][j][q] = 0.f;

    const int KT = K / 32;

    auto prefetch = [&](int s, int kt) {
        const __nv_bfloat16* Ag = A + (long)row0 * lda + kt * 32;
        const __nv_bfloat16* Bg = B + (long)col0 * ldb + kt * 32;
        #pragma unroll
        for (int i = 0; i < 2; i++) {
            int l = tid + 256 * i;
            int r = l >> 2, c = (l & 3) << 3;
            CP_ASYNC16(asu + s * STG + (uint32_t)(r * LDSB + c) * 2, Ag + (long)r * lda + c);
            CP_ASYNC16(bsu + s * STG + (uint32_t)(r * LDSB + c) * 2, Bg + (long)r * ldb + c);
        }
        CP_COMMIT();
    };

    prefetch(0, 0);

    for (int kt = 0; kt < KT; kt++) {
        if (kt + 1 < KT) { prefetch((kt + 1) & 1, kt + 1); CP_WAIT1(); }
        else             { CP_WAIT0(); }
        __syncthreads();

        const uint32_t ab = asu + (uint32_t)(kt & 1) * STG;
        const uint32_t bb = bsu + (uint32_t)(kt & 1) * STG;

        #pragma unroll
        for (int k16 = 0; k16 < 2; k16++) {
            uint32_t af[4][4];
            #pragma unroll
            for (int im = 0; im < 4; im++) {
                int m = wm * 64 + im * 16 + (lane & 15);
                uint32_t addr = ab + (uint32_t)m * (LDSB * 2) + k16 * 32 + ((lane >> 4) & 1) * 16;
                ldsm4(af[im][0], af[im][1], af[im][2], af[im][3], addr);
            }
            #pragma unroll
            for (int ig = 0; ig < 2; ig++) {
                uint32_t bf[4];
                int n = wn * 32 + ig * 16 + (lane & 7) + ((lane >> 4) & 1) * 8;
                uint32_t addr = bb + (uint32_t)n * (LDSB * 2) + k16 * 32 + ((lane >> 3) & 1) * 16;
                ldsm4(bf[0], bf[1], bf[2], bf[3], addr);
                #pragma unroll
                for (int im = 0; im < 4; im++) {
                    mma_bf16(acc[im][ig * 2 + 0], af[im], bf + 0);
                    mma_bf16(acc[im][ig * 2 + 1], af[im], bf + 2);
                }
            }
        }
        __syncthreads();
    }

    #pragma unroll
    for (int im = 0; im < 4; im++) {
        int mrow = row0 + wm * 64 + im * 16 + (lane >> 2);
        #pragma unroll
        for (int jg = 0; jg < 4; jg++) {
            int ncol = col0 + wn * 32 + (jg >> 1) * 16 + (jg & 1) * 8 + 2 * (lane & 3);
            float b0 = 0.f, b1 = 0.f;
            if (bias) { b0 = bias[ncol]; b1 = bias[ncol + 1]; }
            #pragma unroll
            for (int half = 0; half < 2; half++) {
                long r = mrow + half * 8;
                float v0 = acc[im][jg][half * 2 + 0] + b0;
                float v1 = acc[im][jg][half * 2 + 1] + b1;
                if (residual) {
                    v0 += residual[r * ldc + ncol];
                    v1 += residual[r * ldc + ncol + 1];
                }
                if (OBF) {
                    __nv_bfloat16* C = (__nv_bfloat16*)Cv;
                    *reinterpret_cast<__nv_bfloat162*>(&C[r * ldc + ncol]) =
                        __floats2bfloat162_rn(v0, v1);
                } else {
                    float* C = (float*)Cv;
                    float2 vv; vv.x = v0; vv.y = v1;
                    *reinterpret_cast<float2*>(&C[r * ldc + ncol]) = vv;
                }
            }
        }
    }
}

// =====================================================================
// Fused FFN-in + SwiGLU: act[m, c] = silu(u)*g, u = h2 @ win_w[c]^T + b[c],
// g = h2 @ win_w[HID+c]^T + b[HID+c].  Block: 128 rows x 64 cols (u AND g).
// 8 warps: wm in {0,1} (64 rows), wn in {0..3} (16 cols). No uv round-trip.
// =====================================================================
__global__ __launch_bounds__(256) void ffn_in_kernel(
    const __nv_bfloat16* __restrict__ A, const __nv_bfloat16* __restrict__ B,
    __nv_bfloat16* __restrict__ act, const float* __restrict__ bias)
{
    constexpr int LDSB = 40;
    constexpr uint32_t ASTG = 128 * LDSB * 2;
    constexpr uint32_t BSTG = 64 * LDSB * 2;

    __shared__ __nv_bfloat16 As[2][128 * LDSB];
    __shared__ __nv_bfloat16 Bu[2][64 * LDSB];
    __shared__ __nv_bfloat16 Bg[2][64 * LDSB];

    const int tid  = threadIdx.x;
    const int lane = tid & 31;
    const int warp = tid >> 5;
    const int wm = warp >> 2;
    const int wn = warp & 3;

    const int row0 = blockIdx.y * 128;
    const int col0 = blockIdx.x * 64;

    const uint32_t asu = (uint32_t)__cvta_generic_to_shared(&As[0][0]);
    const uint32_t buu = (uint32_t)__cvta_generic_to_shared(&Bu[0][0]);
    const uint32_t bgu = (uint32_t)__cvta_generic_to_shared(&Bg[0][0]);

    float accu[4][2][4], accg[4][2][4];
    #pragma unroll
    for (int i = 0; i < 4; i++)
        #pragma unroll
        for (int j = 0; j < 2; j++)
            #pragma unroll
            for (int q = 0; q < 4; q++) { accu[i][j][q] = 0.f; accg[i][j][q] = 0.f; }

    const int KT = DD / 32;   // 24

    auto prefetch = [&](int s, int kt) {
        const __nv_bfloat16* Ag = A + (long)row0 * DD + kt * 32;
        #pragma unroll
        for (int i = 0; i < 2; i++) {
            int l = tid + 256 * i;
            int r = l >> 2, c = (l & 3) << 3;
            CP_ASYNC16(asu + s * ASTG + (uint32_t)(r * LDSB + c) * 2, Ag + (long)r * DD + c);
        }
        {
            int r = tid >> 2, c = (tid & 3) << 3;
            const __nv_bfloat16* Bgu = B + (long)(col0 + r) * DD + kt * 32 + c;
            const __nv_bfloat16* Bgg = B + (long)(HID + col0 + r) * DD + kt * 32 + c;
            CP_ASYNC16(buu + s * BSTG + (uint32_t)(r * LDSB + c) * 2, Bgu);
            CP_ASYNC16(bgu + s * BSTG + (uint32_t)(r * LDSB + c) * 2, Bgg);
        }
        CP_COMMIT();
    };

    prefetch(0, 0);

    for (int kt = 0; kt < KT; kt++) {
        if (kt + 1 < KT) { prefetch((kt + 1) & 1, kt + 1); CP_WAIT1(); }
        else             { CP_WAIT0(); }
        __syncthreads();

        const uint32_t ab  = asu + (uint32_t)(kt & 1) * ASTG;
        const uint32_t bub = buu + (uint32_t)(kt & 1) * BSTG;
        const uint32_t bgb = bgu + (uint32_t)(kt & 1) * BSTG;

        #pragma unroll
        for (int k16 = 0; k16 < 2; k16++) {
            uint32_t af[4][4];
            #pragma unroll
            for (int im = 0; im < 4; im++) {
                int m = wm * 64 + im * 16 + (lane & 15);
                uint32_t addr = ab + (uint32_t)m * (LDSB * 2) + k16 * 32 + ((lane >> 4) & 1) * 16;
                ldsm4(af[im][0], af[im][1], af[im][2], af[im][3], addr);
            }
            int n = wn * 16 + (lane & 7) + ((lane >> 4) & 1) * 8;
            uint32_t off = (uint32_t)n * (LDSB * 2) + k16 * 32 + ((lane >> 3) & 1) * 16;
            uint32_t bfu[4], bfg[4];
            ldsm4(bfu[0], bfu[1], bfu[2], bfu[3], bub + off);
            ldsm4(bfg[0], bfg[1], bfg[2], bfg[3], bgb + off);
            #pragma unroll
            for (int im = 0; im < 4; im++) {
                mma_bf16(accu[im][0], af[im], bfu + 0);
                mma_bf16(accu[im][1], af[im], bfu + 2);
                mma_bf16(accg[im][0], af[im], bfg + 0);
                mma_bf16(accg[im][1], af[im], bfg + 2);
            }
        }
        __syncthreads();
    }

    // ---- epilogue: silu(u) * g -> bf16 ----
    #pragma unroll
    for (int im = 0; im < 4; im++) {
        int mrow = row0 + wm * 64 + im * 16 + (lane >> 2);
        #pragma unroll
        for (int jg = 0; jg < 2; jg++) {
            int col = col0 + wn * 16 + jg * 8 + 2 * (lane & 3);
            float bu0 = bias[col],       bu1 = bias[col + 1];
            float bg0 = bias[HID + col], bg1 = bias[HID + col + 1];
            #pragma unroll
            for (int half = 0; half < 2; half++) {
                long r = mrow + half * 8;
                float u0 = accu[im][jg][half * 2 + 0] + bu0;
                float u1 = accu[im][jg][half * 2 + 1] + bu1;
                float g0 = accg[im][jg][half * 2 + 0] + bg0;
                float g1 = accg[im][jg][half * 2 + 1] + bg1;
                float a0 = u0 / (1.f + __expf(-u0)) * g0;
                float a1 = u1 / (1.f + __expf(-u1)) * g1;
                *reinterpret_cast<__nv_bfloat162*>(&act[r * HID + col]) =
                    __floats2bfloat162_rn(a0, a1);
            }
        }
    }
}

// =====================================================================
// Fused flash attention, bf16 MMA (unchanged from round 7).
// =====================================================================
struct FaSmem {
    __nv_bfloat16 Qs[128 * 72];
    __nv_bfloat16 Ks[2][64 * 72];
    __nv_bfloat16 Vs[2][64 * 72];
    __nv_bfloat16 Ps[8][16 * 72];
    float psc[2][64];
};
#define FA_SMEM_BYTES (sizeof(FaSmem))

__global__ __launch_bounds__(256, 2) void fa_kernel(
    const __nv_bfloat16* __restrict__ qkv, const float* __restrict__ p,
    float* __restrict__ o)
{
    extern __shared__ float smf[];
    FaSmem* sm = reinterpret_cast<FaSmem*>(smf);
    const int tid = threadIdx.x, lane = tid & 31, warp = tid >> 5;
    const int mt = blockIdx.x;
    const int z  = blockIdx.y;
    const int zb = z / HH, zh = z % HH;

    const __nv_bfloat16* Qg = qkv + ((long)zb * NN_ + mt * 128) * D3 + zh * 64;
    const __nv_bfloat16* Kg = qkv + (long)zb * NN_ * D3 + DD + zh * 64;
    const __nv_bfloat16* Vg = qkv + (long)zb * NN_ * D3 + 2 * DD + zh * 64;
    const float* pg = p + (long)z * NN_;

    const uint32_t qsu  = (uint32_t)__cvta_generic_to_shared(sm->Qs);
    const uint32_t ksu  = (uint32_t)__cvta_generic_to_shared(sm->Ks[0]);
    const uint32_t vsu  = (uint32_t)__cvta_generic_to_shared(sm->Vs[0]);
    const uint32_t psu  = (uint32_t)__cvta_generic_to_shared(sm->Ps[warp]);
    const uint32_t pscu = (uint32_t)__cvta_generic_to_shared(sm->psc[0]);
    constexpr uint32_t KVB = 64 * 72 * 2;

    auto prep = [&](int s, int j) {
        #pragma unroll
        for (int i = 0; i < 2; i++) {
            int l = tid + 256 * i;
            int r = l >> 3, c = (l & 7) << 3;
            CP_ASYNC16(ksu + (uint32_t)s * KVB + (uint32_t)(r * 72 + c) * 2,
                       Kg + (long)(j * 64 + r) * D3 + c);
            CP_ASYNC16(vsu + (uint32_t)s * KVB + (uint32_t)(r * 72 + c) * 2,
                       Vg + (long)(j * 64 + r) * D3 + c);
        }
        if (tid < 16)
            CP_ASYNC16(pscu + (uint32_t)s * 256 + tid * 16, pg + j * 64 + tid * 4);
        CP_COMMIT();
    };

    #pragma unroll
    for (int i = 0; i < 4; i++) {
        int l = tid + 256 * i;
        int r = l >> 3, c = (l & 7) << 3;
        CP_ASYNC16(qsu + (uint32_t)(r * 72 + c) * 2, Qg + (long)r * D3 + c);
    }
    prep(0, 0);

    float m0 = -1e30f, m1 = -1e30f, l0 = 0.f, l1 = 0.f;
    float oacc[4][2][4];
    #pragma unroll
    for (int a = 0; a < 4; a++)
        #pragma unroll
        for (int b = 0; b < 2; b++)
            #pragma unroll
            for (int q = 0; q < 4; q++) oacc[a][b][q] = 0.f;

    for (int j = 0; j < 16; j++) {
        const int s = j & 1;
        __syncthreads();
        if (j < 15) { prep(s ^ 1, j + 1); CP_WAIT1(); }
        else        { CP_WAIT0(); }
        __syncthreads();

        float sacc[4][2][4];
        #pragma unroll
        for (int a = 0; a < 4; a++)
            #pragma unroll
            for (int b = 0; b < 2; b++)
                #pragma unroll
                for (int q = 0; q < 4; q++) sacc[a][b][q] = 0.f;

        const uint32_t ksb = ksu + (uint32_t)s * KVB;
        #pragma unroll
        for (int k16 = 0; k16 < 4; k16++) {
            uint32_t af[4];
            {
                int m = warp * 16 + (lane & 15);
                uint32_t addr = qsu + (uint32_t)m * 144 + k16 * 32 + ((lane >> 4) & 1) * 16;
                ldsm4(af[0], af[1], af[2], af[3], addr);
            }
            #pragma unroll
            for (int ig = 0; ig < 4; ig++) {
                uint32_t bf[4];
                int n = ig * 16 + (lane & 7) + ((lane >> 4) & 1) * 8;
                uint32_t addr = ksb + (uint32_t)n * 144 + k16 * 32 + ((lane >> 3) & 1) * 16;
                ldsm4(bf[0], bf[1], bf[2], bf[3], addr);
                mma_bf16(sacc[ig][0], af, bf + 0);
                mma_bf16(sacc[ig][1], af, bf + 2);
            }
        }

        #pragma unroll
        for (int ig = 0; ig < 4; ig++)
            #pragma unroll
            for (int hf = 0; hf < 2; hf++) {
                int cb = ig * 16 + hf * 8 + 2 * (lane & 3);
                float p0 = sm->psc[s][cb], p1 = sm->psc[s][cb + 1];
                sacc[ig][hf][0] = sacc[ig][hf][0] * 0.125f - p0;
                sacc[ig][hf][1] = sacc[ig][hf][1] * 0.125f - p1;
                sacc[ig][hf][2] = sacc[ig][hf][2] * 0.125f - p0;
                sacc[ig][hf][3] = sacc[ig][hf][3] * 0.125f - p1;
            }

        float mx0 = -1e30f, mx1 = -1e30f;
        #pragma unroll
        for (int ig = 0; ig < 4; ig++)
            #pragma unroll
            for (int hf = 0; hf < 2; hf++) {
                mx0 = fmaxf(mx0, fmaxf(sacc[ig][hf][0], sacc[ig][hf][1]));
                mx1 = fmaxf(mx1, fmaxf(sacc[ig][hf][2], sacc[ig][hf][3]));
            }
        #pragma unroll
        for (int off = 1; off <= 2; off <<= 1) {
            mx0 = fmaxf(mx0, __shfl_xor_sync(0xffffffffu, mx0, off));
            mx1 = fmaxf(mx1, __shfl_xor_sync(0xffffffffu, mx1, off));
        }
        float mn0 = fmaxf(m0, mx0), mn1 = fmaxf(m1, mx1);
        float f0 = __expf(m0 - mn0), f1 = __expf(m1 - mn1);
        float s0 = 0.f, s1 = 0.f;
        #pragma unroll
        for (int ig = 0; ig < 4; ig++)
            #pragma unroll
            for (int hf = 0; hf < 2; hf++) {
                sacc[ig][hf][0] = __expf(sacc[ig][hf][0] - mn0);
                sacc[ig][hf][1] = __expf(sacc[ig][hf][1] - mn0);
                sacc[ig][hf][2] = __expf(sacc[ig][hf][2] - mn1);
                sacc[ig][hf][3] = __expf(sacc[ig][hf][3] - mn1);
                s0 += sacc[ig][hf][0] + sacc[ig][hf][1];
                s1 += sacc[ig][hf][2] + sacc[ig][hf][3];
            }
        #pragma unroll
        for (int off = 1; off <= 2; off <<= 1) {
            s0 += __shfl_xor_sync(0xffffffffu, s0, off);
            s1 += __shfl_xor_sync(0xffffffffu, s1, off);
        }
        l0 = l0 * f0 + s0;  l1 = l1 * f1 + s1;
        m0 = mn0;           m1 = mn1;
        #pragma unroll
        for (int ig = 0; ig < 4; ig++)
            #pragma unroll
            for (int hf = 0; hf < 2; hf++) {
                oacc[ig][hf][0] *= f0; oacc[ig][hf][1] *= f0;
                oacc[ig][hf][2] *= f1; oacc[ig][hf][3] *= f1;
            }

        {
            __nv_bfloat16* psw = sm->Ps[warp];
            int r0 = lane >> 2;
            #pragma unroll
            for (int ig = 0; ig < 4; ig++)
                #pragma unroll
                for (int hf = 0; hf < 2; hf++) {
                    int cb = ig * 16 + hf * 8 + 2 * (lane & 3);
                    *reinterpret_cast<__nv_bfloat162*>(&psw[r0 * 72 + cb]) =
                        __floats2bfloat162_rn(sacc[ig][hf][0], sacc[ig][hf][1]);
                    *reinterpret_cast<__nv_bfloat162*>(&psw[(r0 + 8) * 72 + cb]) =
                        __floats2bfloat162_rn(sacc[ig][hf][2], sacc[ig][hf][3]);
                }
        }
        __syncwarp();

        const uint32_t vsb = vsu + (uint32_t)s * KVB;
        #pragma unroll
        for (int k16 = 0; k16 < 4; k16++) {
            uint32_t af[4];
            {
                int m = lane & 15;
                uint32_t addr = psu + (uint32_t)m * 144 + k16 * 32 + ((lane >> 4) & 1) * 16;
                ldsm4(af[0], af[1], af[2], af[3], addr);
            }
            #pragma unroll
            for (int ig = 0; ig < 4; ig++) {
                uint32_t bf[4];
                int key = k16 * 16 + ((lane >> 3) & 1) * 8 + (lane & 7);
                uint32_t addr = vsb + (uint32_t)key * 144 + ig * 32 + ((lane >> 4) & 1) * 16;
                ldsm4t(bf[0], bf[1], bf[2], bf[3], addr);
                mma_bf16(oacc[ig][0], af, bf + 0);
                mma_bf16(oacc[ig][1], af, bf + 2);
            }
        }
    }

    float inv0 = 1.f / l0, inv1 = 1.f / l1;
    long gi = (long)zb * NN_ + mt * 128 + warp * 16 + (lane >> 2);
    #pragma unroll
    for (int ig = 0; ig < 4; ig++)
        #pragma unroll
        for (int hf = 0; hf < 2; hf++) {
            int c = zh * 64 + ig * 16 + hf * 8 + 2 * (lane & 3);
            float2 a; a.x = oacc[ig][hf][0] * inv0; a.y = oacc[ig][hf][1] * inv0;
            float2 b; b.x = oacc[ig][hf][2] * inv1; b.y = oacc[ig][hf][3] * inv1;
            *reinterpret_cast<float2*>(&o[gi * DD + c]) = a;
            *reinterpret_cast<float2*>(&o[(gi + 8) * DD + c]) = b;
        }
}

// ---------------- launch ----------------
extern "C" void kernel_launch(void* const* d_in, const int* in_sizes, int n_in,
                              void* d_out, int out_size)
{
    const float* x      = (const float*)d_in[0];
    const float* coords = (const float*)d_in[1];
    const float* ln1_g  = (const float*)d_in[2];
    const float* ln1_b  = (const float*)d_in[3];
    const float* qkv_w  = (const float*)d_in[4];
    const float* qkv_b  = (const float*)d_in[5];
    const float* rel_w  = (const float*)d_in[6];
    const float* ln2_g  = (const float*)d_in[7];
    const float* ln2_b  = (const float*)d_in[8];
    const float* win_w  = (const float*)d_in[9];
    const float* win_b  = (const float*)d_in[10];
    const float* wout_w = (const float*)d_in[11];
    const float* wout_b = (const float*)d_in[12];
    float* out = (float*)d_out;

    float* S = nullptr;
    cudaGetSymbolAddress((void**)&S, g_scratch);
    float* p   = S + OFF_P;
    float* xm  = S + OFF_XM;
    float* o   = S + OFF_O;
    __nv_bfloat16* qkvbf = (__nv_bfloat16*)(S + OFF_QKVBF);
    __nv_bfloat16* hbf   = (__nv_bfloat16*)(S + OFF_HBF);
    __nv_bfloat16* wqbf  = (__nv_bfloat16*)(S + OFF_WQ);
    __nv_bfloat16* wibf  = (__nv_bfloat16*)(S + OFF_WI);
    __nv_bfloat16* wobf  = (__nv_bfloat16*)(S + OFF_WO);
    __nv_bfloat16* actbf = (__nv_bfloat16*)(S + OFF_ACTBF);

    cudaFuncSetAttribute(fa_kernel, cudaFuncAttributeMaxDynamicSharedMemorySize,
                         (int)FA_SMEM_BYTES);

    // 0) weight converts
    cvt_kernel<<<(D3*DD)/1024, 256>>>(qkv_w, wqbf, D3*DD);
    cvt_kernel<<<(2*HID*DD)/1024, 256>>>(win_w, wibf, 2*HID*DD);
    cvt_kernel<<<(DD*HID)/1024, 256>>>(wout_w, wobf, DD*HID);

    // 1) h = LN1(x) -> bf16
    ln_kernel<<<ROWS, 256>>>(x, nullptr, ln1_g, ln1_b, hbf, nullptr);

    // 2) qkv = h @ qkv_w^T + qkv_b -> bf16
    tgemm<true><<<dim3(D3/128, ROWS/128), 256>>>(
        hbf, wqbf, qkvbf, DD, DD, D3, DD, qkv_b, nullptr);

    // 3) p[b,h,n]
    p_kernel<<<(ZHN*NN_)/256, 256>>>(coords, rel_w, p);

    // 4-6) fused attention -> o (fp32)
    fa_kernel<<<dim3(8, ZHN), 256, FA_SMEM_BYTES>>>(qkvbf, p, o);

    // 7) xm = x + o ; h2 = LN2(xm) -> bf16
    ln_kernel<<<ROWS, 256>>>(x, o, ln2_g, ln2_b, hbf, xm);

    // 8+9) act = silu(h2 Wu^T + bu) * (h2 Wg^T + bg) -> bf16 (fused, no uv)
    ffn_in_kernel<<<dim3(HID/64, ROWS/128), 256>>>(hbf, wibf, actbf, win_b);

    // 10) out = act @ wout_w^T + wout_b + xm -> fp32
    tgemm<false><<<dim3(DD/128, ROWS/128), 256>>>(
        actbf, wobf, out, HID, HID, DD, HID, wout_b, xm);
}